// round 6
// baseline (speedup 1.0000x reference)
#include <cuda_runtime.h>
#include <cuda_bf16.h>
#include <cuda_fp16.h>
#include <cstdint>

#define H 128
#define NMAX 100000

// Scratch: per-node A = z@W1_top + b1 (cols 0..127), B = z@W1_bot (cols 128..255), fp16
__device__ __align__(16) __half g_ABh[(size_t)NMAX * 256];
__device__ int g_idx_is64;
// Pre-transposed Wcat^T as bf16 hi/lo: layout [n][k], n in [0,256), k in [0,128)
__device__ __align__(16) __nv_bfloat16 g_Wt_hi[256 * 128];
__device__ __align__(16) __nv_bfloat16 g_Wt_lo[256 * 128];

// ---------------- index dtype detection ----------------
__global__ void detect_idx_kernel(const long long* __restrict__ p, int n64) {
    int bad = 0;
    for (int i = threadIdx.x; i < n64; i += blockDim.x) {
        long long v = p[i];
        if (v < 0 || v >= NMAX) bad = 1;
    }
    bad = __syncthreads_or(bad);
    if (threadIdx.x == 0) g_idx_is64 = bad ? 0 : 1;
}

// ---------------- W^T prep: Wt[n][k] = Wcat[k][n], split to bf16 hi/lo ----------------
__global__ void prep_w_kernel(const float* __restrict__ W1) {
    int idx = blockIdx.x * blockDim.x + threadIdx.x;   // 32768
    if (idx >= 256 * 128) return;
    int n = idx & 255;
    int k = idx >> 8;
    float v = (n < 128) ? W1[(size_t)k * 128 + n] : W1[(size_t)(k + 128) * 128 + (n - 128)];
    __nv_bfloat16 hi = __float2bfloat16(v);
    __nv_bfloat16 lo = __float2bfloat16(v - __bfloat162float(hi));
    g_Wt_hi[(size_t)n * 128 + k] = hi;
    g_Wt_lo[(size_t)n * 128 + k] = lo;
}

// ---------------- bf16-split tensor-core GEMM via mma.sync ----------------
// CTA tile: M=64, N=128 (half selected by blockIdx.y), K=128 resident.
#define ASTRIDE 136   // bf16 elems per SMEM row

__device__ __forceinline__ void mma16816(float* d, const uint32_t* a, const uint32_t* b) {
    asm volatile(
        "mma.sync.aligned.m16n8k16.row.col.f32.bf16.bf16.f32 "
        "{%0,%1,%2,%3}, {%4,%5,%6,%7}, {%8,%9}, {%0,%1,%2,%3};"
        : "+f"(d[0]), "+f"(d[1]), "+f"(d[2]), "+f"(d[3])
        : "r"(a[0]), "r"(a[1]), "r"(a[2]), "r"(a[3]), "r"(b[0]), "r"(b[1]));
}

__global__ __launch_bounds__(256, 2) void node_gemm_mma(
    const float* __restrict__ z,
    const float* __restrict__ b1,
    int n_nodes)
{
    extern __shared__ __align__(16) unsigned char smem[];
    __nv_bfloat16* Ah = (__nv_bfloat16*)smem;            // [64][ASTRIDE]
    __nv_bfloat16* Al = Ah + 64 * ASTRIDE;
    __nv_bfloat16* Bh = Al + 64 * ASTRIDE;               // [128 n][ASTRIDE k]
    __nv_bfloat16* Bl = Bh + 128 * ASTRIDE;

    const int tid = threadIdx.x;
    const int wid = tid >> 5;
    const int lane = tid & 31;
    const int m0 = blockIdx.x * 64;
    const int half = blockIdx.y;

    // ---- load z tile [64 x 128] fp32 -> bf16 hi/lo ----
    #pragma unroll
    for (int i = 0; i < 8; i++) {
        int idx = tid + i * 256;        // 0..2047 float4 slots
        int r = idx >> 5;
        int c4 = idx & 31;
        float4 v = make_float4(0.f, 0.f, 0.f, 0.f);
        if (m0 + r < n_nodes)
            v = *(const float4*)(z + (size_t)(m0 + r) * H + c4 * 4);
        __nv_bfloat16 h0 = __float2bfloat16(v.x), h1 = __float2bfloat16(v.y);
        __nv_bfloat16 h2 = __float2bfloat16(v.z), h3 = __float2bfloat16(v.w);
        __nv_bfloat16 l0 = __float2bfloat16(v.x - __bfloat162float(h0));
        __nv_bfloat16 l1 = __float2bfloat16(v.y - __bfloat162float(h1));
        __nv_bfloat16 l2 = __float2bfloat16(v.z - __bfloat162float(h2));
        __nv_bfloat16 l3 = __float2bfloat16(v.w - __bfloat162float(h3));
        uint2 uh, ul;
        uh.x = ((uint32_t)__bfloat16_as_ushort(h1) << 16) | __bfloat16_as_ushort(h0);
        uh.y = ((uint32_t)__bfloat16_as_ushort(h3) << 16) | __bfloat16_as_ushort(h2);
        ul.x = ((uint32_t)__bfloat16_as_ushort(l1) << 16) | __bfloat16_as_ushort(l0);
        ul.y = ((uint32_t)__bfloat16_as_ushort(l3) << 16) | __bfloat16_as_ushort(l2);
        *(uint2*)((unsigned char*)Ah + r * (ASTRIDE * 2) + c4 * 8) = uh;
        *(uint2*)((unsigned char*)Al + r * (ASTRIDE * 2) + c4 * 8) = ul;
    }

    // ---- copy pre-transposed W images for this half (128 n-rows) ----
    {
        const uint4* shi = (const uint4*)(g_Wt_hi + (size_t)half * 128 * 128);
        const uint4* slo = (const uint4*)(g_Wt_lo + (size_t)half * 128 * 128);
        #pragma unroll
        for (int i = 0; i < 8; i++) {
            int idx = tid + i * 256;    // 0..2047
            int r = idx >> 4;
            int q = idx & 15;
            *(uint4*)((unsigned char*)Bh + r * (ASTRIDE * 2) + q * 16) = shi[r * 16 + q];
            *(uint4*)((unsigned char*)Bl + r * (ASTRIDE * 2) + q * 16) = slo[r * 16 + q];
        }
    }
    __syncthreads();

    // ---- compute: 8 warps, warp tile 32(M) x 32(N) ----
    const int wm = wid & 1;             // 2 warps along M
    const int wn = wid >> 1;            // 4 warps along N
    const int gr = lane >> 2;
    const int cc = lane & 3;

    float accP[2][4][4], accQ[2][4][4];
    #pragma unroll
    for (int a = 0; a < 2; a++)
        #pragma unroll
        for (int b = 0; b < 4; b++)
            #pragma unroll
            for (int c = 0; c < 4; c++) { accP[a][b][c] = 0.f; accQ[a][b][c] = 0.f; }

    #pragma unroll
    for (int ks = 0; ks < 8; ks++) {
        const int kb = ks * 32 + cc * 4;
        uint32_t ah[2][4], al[2][4];
        #pragma unroll
        for (int mt = 0; mt < 2; mt++) {
            int row = wm * 32 + mt * 16 + gr;
            const unsigned char* pAh = (const unsigned char*)Ah + kb;
            const unsigned char* pAl = (const unsigned char*)Al + kb;
            ah[mt][0] = *(const uint32_t*)(pAh + (row)     * (ASTRIDE * 2));
            ah[mt][1] = *(const uint32_t*)(pAh + (row + 8) * (ASTRIDE * 2));
            ah[mt][2] = *(const uint32_t*)(pAh + (row)     * (ASTRIDE * 2) + 16);
            ah[mt][3] = *(const uint32_t*)(pAh + (row + 8) * (ASTRIDE * 2) + 16);
            al[mt][0] = *(const uint32_t*)(pAl + (row)     * (ASTRIDE * 2));
            al[mt][1] = *(const uint32_t*)(pAl + (row + 8) * (ASTRIDE * 2));
            al[mt][2] = *(const uint32_t*)(pAl + (row)     * (ASTRIDE * 2) + 16);
            al[mt][3] = *(const uint32_t*)(pAl + (row + 8) * (ASTRIDE * 2) + 16);
        }
        #pragma unroll
        for (int nt = 0; nt < 4; nt++) {
            int nrow = wn * 32 + nt * 8 + gr;
            const unsigned char* pB  = (const unsigned char*)Bh + nrow * (ASTRIDE * 2) + kb;
            const unsigned char* pBl = (const unsigned char*)Bl + nrow * (ASTRIDE * 2) + kb;
            uint32_t bh[2], bl[2];
            bh[0] = *(const uint32_t*)(pB);
            bh[1] = *(const uint32_t*)(pB + 16);
            bl[0] = *(const uint32_t*)(pBl);
            bl[1] = *(const uint32_t*)(pBl + 16);
            #pragma unroll
            for (int mt = 0; mt < 2; mt++) {
                mma16816(accP[mt][nt], ah[mt], bh);   // hi*hi  -> accP
                mma16816(accQ[mt][nt], al[mt], bh);   // lo*hi  -> accQ
                mma16816(accQ[mt][nt], ah[mt], bl);   // hi*lo  -> accQ
            }
        }
    }

    // ---- epilogue: half2 writes, b1 fused on half 0 ----
    #pragma unroll
    for (int mt = 0; mt < 2; mt++) {
        #pragma unroll
        for (int nt = 0; nt < 4; nt++) {
            int nloc = wn * 32 + nt * 8 + cc * 2;
            int ncol = half * 128 + nloc;
            float bx = 0.f, by = 0.f;
            if (half == 0) {
                float2 bb = __ldg((const float2*)(b1 + nloc));
                bx = bb.x; by = bb.y;
            }
            int row0 = m0 + wm * 32 + mt * 16 + gr;
            if (row0 < n_nodes) {
                __half2 v = __floats2half2_rn(accP[mt][nt][0] + accQ[mt][nt][0] + bx,
                                              accP[mt][nt][1] + accQ[mt][nt][1] + by);
                *(__half2*)(g_ABh + (size_t)row0 * 256 + ncol) = v;
            }
            int row1 = row0 + 8;
            if (row1 < n_nodes) {
                __half2 v = __floats2half2_rn(accP[mt][nt][2] + accQ[mt][nt][2] + bx,
                                              accP[mt][nt][3] + accQ[mt][nt][3] + by);
                *(__half2*)(g_ABh + (size_t)row1 * 256 + ncol) = v;
            }
        }
    }
}

#define SMEM_GEMM ((2 * 64 + 2 * 128) * ASTRIDE * 2)   // 104448 bytes

// ---------------- Edge pass: 8 lanes per edge, 4 edges per warp ----------------
__global__ __launch_bounds__(256) void edge_kernel(
    const void* __restrict__ eli_raw,
    const float* __restrict__ W2,
    const float* __restrict__ b2,
    float* __restrict__ out,
    int E, int n_nodes)
{
    __shared__ float w2s[128];
    const int tid = threadIdx.x;
    if (tid < 128) w2s[tid] = W2[tid];
    __syncthreads();

    const int lane = tid & 31;
    const int warp = tid >> 5;
    const int e0 = (blockIdx.x * 8 + warp) * 4;
    if (e0 >= E) return;

    // lanes 0..3 load r for edges e0..e0+3; lanes 4..7 load c
    int vidx = 0;
    if (lane < 8) {
        int e = e0 + (lane & 3);
        if (e >= E) e = E - 1;
        size_t off = (lane >= 4) ? ((size_t)E + e) : (size_t)e;
        if (g_idx_is64) vidx = (int)((const long long*)eli_raw)[off];
        else            vidx = ((const int*)eli_raw)[off];
        vidx = min(max(vidx, 0), n_nodes - 1);
    }

    const int g = lane >> 3;            // edge group 0..3
    const int w = lane & 7;             // lane within group
    const int r = __shfl_sync(0xffffffffu, vidx, g);
    const int c = __shfl_sync(0xffffffffu, vidx, 4 + g);

    const uint4* pa = (const uint4*)(g_ABh + (size_t)r * 256) + w;         // A-half
    const uint4* pb = (const uint4*)(g_ABh + (size_t)c * 256 + 128) + w;   // B-half
    uint4 a0 = pa[0], a1 = pa[8];
    uint4 b0 = pb[0], b1 = pb[8];

    // w2 slices for this lane: [8w..8w+7] and [64+8w..64+8w+7]
    float4 w00 = *(const float4*)(w2s + 8 * w);
    float4 w01 = *(const float4*)(w2s + 8 * w + 4);
    float4 w10 = *(const float4*)(w2s + 64 + 8 * w);
    float4 w11 = *(const float4*)(w2s + 64 + 8 * w + 4);

    const __half2 z2 = __float2half2_rn(0.f);
    float s = 0.f;
    {
        // 8 halves: a0/b0 with w00,w01
        __half2 h;
        float2 f;
        h = __hmax2(__hadd2(*(__half2*)&a0.x, *(__half2*)&b0.x), z2); f = __half22float2(h);
        s = fmaf(f.x, w00.x, fmaf(f.y, w00.y, s));
        h = __hmax2(__hadd2(*(__half2*)&a0.y, *(__half2*)&b0.y), z2); f = __half22float2(h);
        s = fmaf(f.x, w00.z, fmaf(f.y, w00.w, s));
        h = __hmax2(__hadd2(*(__half2*)&a0.z, *(__half2*)&b0.z), z2); f = __half22float2(h);
        s = fmaf(f.x, w01.x, fmaf(f.y, w01.y, s));
        h = __hmax2(__hadd2(*(__half2*)&a0.w, *(__half2*)&b0.w), z2); f = __half22float2(h);
        s = fmaf(f.x, w01.z, fmaf(f.y, w01.w, s));
        // 8 halves: a1/b1 with w10,w11
        h = __hmax2(__hadd2(*(__half2*)&a1.x, *(__half2*)&b1.x), z2); f = __half22float2(h);
        s = fmaf(f.x, w10.x, fmaf(f.y, w10.y, s));
        h = __hmax2(__hadd2(*(__half2*)&a1.y, *(__half2*)&b1.y), z2); f = __half22float2(h);
        s = fmaf(f.x, w10.z, fmaf(f.y, w10.w, s));
        h = __hmax2(__hadd2(*(__half2*)&a1.z, *(__half2*)&b1.z), z2); f = __half22float2(h);
        s = fmaf(f.x, w11.x, fmaf(f.y, w11.y, s));
        h = __hmax2(__hadd2(*(__half2*)&a1.w, *(__half2*)&b1.w), z2); f = __half22float2(h);
        s = fmaf(f.x, w11.z, fmaf(f.y, w11.w, s));
    }

    // reduce within 8-lane group
    #pragma unroll
    for (int o = 4; o; o >>= 1) s += __shfl_xor_sync(0xffffffffu, s, o);

    if (w == 0 && e0 + g < E) out[e0 + g] = s + __ldg(b2);
}

extern "C" void kernel_launch(void* const* d_in, const int* in_sizes, int n_in,
                              void* d_out, int out_size)
{
    const float* z   = (const float*)d_in[0];
    const void*  eli = d_in[1];
    const float* W1  = (const float*)d_in[2];
    const float* b1  = (const float*)d_in[3];
    const float* W2  = (const float*)d_in[4];
    const float* b2  = (const float*)d_in[5];
    float*       out = (float*)d_out;

    const int n_nodes = in_sizes[0] / H;
    const int E = out_size;

    int n64 = E < 1024 ? E : 1024;
    detect_idx_kernel<<<1, 256>>>((const long long*)eli, n64);

    prep_w_kernel<<<32, 1024>>>(W1);

    cudaFuncSetAttribute(node_gemm_mma, cudaFuncAttributeMaxDynamicSharedMemorySize,
                         SMEM_GEMM);
    dim3 g1((n_nodes + 63) / 64, 2);
    node_gemm_mma<<<g1, 256, SMEM_GEMM>>>(z, b1, n_nodes);

    int blocks = (E + 31) / 32;
    edge_kernel<<<blocks, 256>>>(eli, W2, b2, out, E, n_nodes);
}

// round 7
// speedup vs baseline: 1.1786x; 1.1786x over previous
#include <cuda_runtime.h>
#include <cuda_fp16.h>
#include <cstdint>

#define H 128
#define NMAX 100000

// Scratch: per-node A = z@W1_top + b1 (cols 0..127), B = z@W1_bot (cols 128..255), fp16
__device__ __align__(16) __half g_ABh[(size_t)NMAX * 256];
__device__ int g_idx_is64;
// Pre-transposed, tf32-rounded Wcat^T: layout [n][k], n in [0,256), k in [0,128)
__device__ __align__(16) float g_Wt[256 * 128];

__device__ __forceinline__ float to_tf32(float x) {
    float r; asm("cvt.rna.tf32.f32 %0, %1;" : "=f"(r) : "f"(x)); return r;
}

// ---------------- merged prep: block 0 detects index dtype, blocks 1..32 build W^T ----------------
__global__ void prep_kernel(const long long* __restrict__ idxp, int n64,
                            const float* __restrict__ W1) {
    if (blockIdx.x == 0) {
        int bad = 0;
        for (int i = threadIdx.x; i < n64; i += blockDim.x) {
            long long v = idxp[i];
            if (v < 0 || v >= NMAX) bad = 1;
        }
        bad = __syncthreads_or(bad);
        if (threadIdx.x == 0) g_idx_is64 = bad ? 0 : 1;
    } else {
        int idx = (blockIdx.x - 1) * blockDim.x + threadIdx.x;   // 0..32767
        int n = idx & 255;
        int k = idx >> 8;
        float v = (n < 128) ? W1[(size_t)k * 128 + n]
                            : W1[(size_t)(k + 128) * 128 + (n - 128)];
        g_Wt[(size_t)n * 128 + k] = to_tf32(v);
    }
}

// ---------------- single-pass tf32 tensor-core GEMM ----------------
// CTA tile: M=128, N=256, K=128 all resident.
#define ASF 132   // fp32 words per SMEM row (132 mod 32 = 4 -> conflict-free frags)

__device__ __forceinline__ void mma_tf32(float* d, const uint32_t* a,
                                         uint32_t b0, uint32_t b1) {
    asm volatile(
        "mma.sync.aligned.m16n8k8.row.col.f32.tf32.tf32.f32 "
        "{%0,%1,%2,%3}, {%4,%5,%6,%7}, {%8,%9}, {%0,%1,%2,%3};"
        : "+f"(d[0]), "+f"(d[1]), "+f"(d[2]), "+f"(d[3])
        : "r"(a[0]), "r"(a[1]), "r"(a[2]), "r"(a[3]), "r"(b0), "r"(b1));
}

__global__ __launch_bounds__(256, 1) void node_gemm_tf32(
    const float* __restrict__ z,
    const float* __restrict__ b1,
    int n_nodes)
{
    extern __shared__ __align__(16) float smem[];
    float* As = smem;              // [128][ASF]
    float* Bs = smem + 128 * ASF;  // [256 n][ASF k]

    const int tid = threadIdx.x;
    const int wid = tid >> 5;
    const int lane = tid & 31;
    const int m0 = blockIdx.x * 128;

    // ---- load z tile [128 x 128], round to tf32 ----
    #pragma unroll
    for (int i = 0; i < 16; i++) {
        int idx = tid + i * 256;            // 0..4095 float4 slots
        int r = idx >> 5;
        int c4 = idx & 31;
        float4 v = make_float4(0.f, 0.f, 0.f, 0.f);
        if (m0 + r < n_nodes)
            v = *(const float4*)(z + (size_t)(m0 + r) * H + c4 * 4);
        v.x = to_tf32(v.x); v.y = to_tf32(v.y);
        v.z = to_tf32(v.z); v.w = to_tf32(v.w);
        *(float4*)(As + r * ASF + c4 * 4) = v;
    }
    // ---- copy pre-rounded W^T [256 x 128] ----
    #pragma unroll
    for (int i = 0; i < 32; i++) {
        int idx = tid + i * 256;            // 0..8191 float4 slots
        int r = idx >> 5;
        int q = idx & 31;
        *(float4*)(Bs + r * ASF + q * 4) = *(const float4*)(g_Wt + (size_t)r * 128 + q * 4);
    }
    __syncthreads();

    // ---- compute: 8 warps, warp tile 32(M) x 128(N) ----
    const int wm = wid & 3;                 // 4 warps along M
    const int wn = wid >> 2;                // 2 warps along N
    const int gr = lane >> 2;
    const int cc = lane & 3;

    float acc[2][16][4];
    #pragma unroll
    for (int a = 0; a < 2; a++)
        #pragma unroll
        for (int b = 0; b < 16; b++)
            #pragma unroll
            for (int c = 0; c < 4; c++) acc[a][b][c] = 0.f;

    #pragma unroll 2
    for (int ks = 0; ks < 16; ks++) {
        const int k0 = ks * 8 + cc;
        uint32_t a[2][4];
        #pragma unroll
        for (int mt = 0; mt < 2; mt++) {
            int row = wm * 32 + mt * 16 + gr;
            a[mt][0] = __float_as_uint(As[row * ASF + k0]);
            a[mt][1] = __float_as_uint(As[(row + 8) * ASF + k0]);
            a[mt][2] = __float_as_uint(As[row * ASF + k0 + 4]);
            a[mt][3] = __float_as_uint(As[(row + 8) * ASF + k0 + 4]);
        }
        #pragma unroll
        for (int nt = 0; nt < 16; nt++) {
            int nrow = wn * 128 + nt * 8 + gr;
            uint32_t b0 = __float_as_uint(Bs[nrow * ASF + k0]);
            uint32_t b1r = __float_as_uint(Bs[nrow * ASF + k0 + 4]);
            #pragma unroll
            for (int mt = 0; mt < 2; mt++)
                mma_tf32(acc[mt][nt], a[mt], b0, b1r);
        }
    }

    // ---- epilogue: half2 writes, b1 fused on cols < 128 ----
    #pragma unroll
    for (int mt = 0; mt < 2; mt++) {
        #pragma unroll
        for (int nt = 0; nt < 16; nt++) {
            int nloc = wn * 128 + nt * 8 + cc * 2;
            float bx = 0.f, by = 0.f;
            if (nloc < 128) {
                float2 bb = __ldg((const float2*)(b1 + nloc));
                bx = bb.x; by = bb.y;
            }
            int row0 = m0 + wm * 32 + mt * 16 + gr;
            if (row0 < n_nodes) {
                __half2 v = __floats2half2_rn(acc[mt][nt][0] + bx, acc[mt][nt][1] + by);
                *(__half2*)(g_ABh + (size_t)row0 * 256 + nloc) = v;
            }
            int row1 = row0 + 8;
            if (row1 < n_nodes) {
                __half2 v = __floats2half2_rn(acc[mt][nt][2] + bx, acc[mt][nt][3] + by);
                *(__half2*)(g_ABh + (size_t)row1 * 256 + nloc) = v;
            }
        }
    }
}

#define SMEM_GEMM ((128 + 256) * ASF * 4)   // 202752 bytes

// ---------------- Edge pass: 4 edges per warp, full-warp dot (R5 version) ----------------
__global__ __launch_bounds__(256) void edge_kernel(
    const void* __restrict__ eli_raw,
    const float* __restrict__ W2,
    const float* __restrict__ b2,
    float* __restrict__ out,
    int E, int n_nodes)
{
    __shared__ float w2s[128];
    const int tid = threadIdx.x;
    if (tid < 128) w2s[tid] = W2[tid];
    __syncthreads();

    const int lane = tid & 31;
    const int warp = tid >> 5;
    const int e0 = (blockIdx.x * 8 + warp) * 4;
    if (e0 >= E) return;

    // lanes 0..3 load r for edges e0..e0+3; lanes 4..7 load c
    int vidx = 0;
    if (lane < 8) {
        int e = e0 + (lane & 3);
        if (e >= E) e = E - 1;
        size_t off = (lane >= 4) ? ((size_t)E + e) : (size_t)e;
        if (g_idx_is64) vidx = (int)((const long long*)eli_raw)[off];
        else            vidx = ((const int*)eli_raw)[off];
        vidx = min(max(vidx, 0), n_nodes - 1);
    }

    uint2 av[4], bv[4];
    #pragma unroll
    for (int i = 0; i < 4; i++) {
        int r = __shfl_sync(0xffffffffu, vidx, i);
        int c = __shfl_sync(0xffffffffu, vidx, 4 + i);
        av[i] = *(const uint2*)(g_ABh + (size_t)r * 256 + lane * 4);
        bv[i] = *(const uint2*)(g_ABh + (size_t)c * 256 + 128 + lane * 4);
    }

    const float4 wv = *(const float4*)(w2s + lane * 4);
    const float bias = __ldg(b2);

    #pragma unroll
    for (int i = 0; i < 4; i++) {
        float2 a0 = __half22float2(*(__half2*)&av[i].x);
        float2 a1 = __half22float2(*(__half2*)&av[i].y);
        float2 c0 = __half22float2(*(__half2*)&bv[i].x);
        float2 c1 = __half22float2(*(__half2*)&bv[i].y);
        float s = fmaxf(a0.x + c0.x, 0.f) * wv.x
                + fmaxf(a0.y + c0.y, 0.f) * wv.y
                + fmaxf(a1.x + c1.x, 0.f) * wv.z
                + fmaxf(a1.y + c1.y, 0.f) * wv.w;
        #pragma unroll
        for (int o = 16; o; o >>= 1) s += __shfl_xor_sync(0xffffffffu, s, o);
        if (lane == 0 && e0 + i < E) out[e0 + i] = s + bias;
    }
}

extern "C" void kernel_launch(void* const* d_in, const int* in_sizes, int n_in,
                              void* d_out, int out_size)
{
    const float* z   = (const float*)d_in[0];
    const void*  eli = d_in[1];
    const float* W1  = (const float*)d_in[2];
    const float* b1  = (const float*)d_in[3];
    const float* W2  = (const float*)d_in[4];
    const float* b2  = (const float*)d_in[5];
    float*       out = (float*)d_out;

    const int n_nodes = in_sizes[0] / H;
    const int E = out_size;

    int n64 = E < 1024 ? E : 1024;
    prep_kernel<<<33, 1024>>>((const long long*)eli, n64, W1);

    cudaFuncSetAttribute(node_gemm_tf32, cudaFuncAttributeMaxDynamicSharedMemorySize,
                         SMEM_GEMM);
    node_gemm_tf32<<<(n_nodes + 127) / 128, 256, SMEM_GEMM>>>(z, b1, n_nodes);

    int blocks = (E + 31) / 32;
    edge_kernel<<<blocks, 256>>>(eli, W2, b2, out, E, n_nodes);
}

// round 8
// speedup vs baseline: 1.2166x; 1.0322x over previous
#include <cuda_runtime.h>
#include <cuda_fp16.h>
#include <cstdint>

#define H 128
#define NMAX 100000

// Scratch: per-node A = z@W1_top + b1 (cols 0..127), B = z@W1_bot (cols 128..255), fp16
__device__ __align__(16) __half g_ABh[(size_t)NMAX * 256];
__device__ int g_idx_is64;
// Pre-transposed, tf32-rounded Wcat^T: layout [n][k], n in [0,256), k in [0,128)
__device__ __align__(16) float g_Wt[256 * 128];

__device__ __forceinline__ float to_tf32(float x) {
    float r; asm("cvt.rna.tf32.f32 %0, %1;" : "=f"(r) : "f"(x)); return r;
}

// ---------------- merged prep: block 0 detects index dtype, blocks 1..32 build W^T ----------------
__global__ void prep_kernel(const long long* __restrict__ idxp, int n64,
                            const float* __restrict__ W1) {
    if (blockIdx.x == 0) {
        int bad = 0;
        for (int i = threadIdx.x; i < n64; i += blockDim.x) {
            long long v = idxp[i];
            if (v < 0 || v >= NMAX) bad = 1;
        }
        bad = __syncthreads_or(bad);
        if (threadIdx.x == 0) g_idx_is64 = bad ? 0 : 1;
    } else {
        int idx = (blockIdx.x - 1) * blockDim.x + threadIdx.x;   // 0..32767
        int n = idx & 255;
        int k = idx >> 8;
        float v = (n < 128) ? W1[(size_t)k * 128 + n]
                            : W1[(size_t)(k + 128) * 128 + (n - 128)];
        g_Wt[(size_t)n * 128 + k] = to_tf32(v);
    }
}

// ---------------- single-pass tf32 tensor-core GEMM ----------------
// CTA tile: M=64, N=128 (half via blockIdx.y), K=128 resident. 2 CTAs/SM.
#define ASF 132   // fp32 words per SMEM row (132 mod 32 = 4 -> conflict-free frags)

__device__ __forceinline__ void mma_tf32(float* d, const uint32_t* a,
                                         uint32_t b0, uint32_t b1) {
    asm volatile(
        "mma.sync.aligned.m16n8k8.row.col.f32.tf32.tf32.f32 "
        "{%0,%1,%2,%3}, {%4,%5,%6,%7}, {%8,%9}, {%0,%1,%2,%3};"
        : "+f"(d[0]), "+f"(d[1]), "+f"(d[2]), "+f"(d[3])
        : "r"(a[0]), "r"(a[1]), "r"(a[2]), "r"(a[3]), "r"(b0), "r"(b1));
}

__device__ __forceinline__ void cp_async16(void* smem_dst, const void* gsrc) {
    uint32_t a;
    asm("{ .reg .u64 t; cvta.to.shared.u64 t, %1; cvt.u32.u64 %0, t; }"
        : "=r"(a) : "l"(smem_dst));
    asm volatile("cp.async.cg.shared.global [%0], [%1], 16;" :: "r"(a), "l"(gsrc) : "memory");
}

__global__ __launch_bounds__(256, 2) void node_gemm_tf32(
    const float* __restrict__ z,
    const float* __restrict__ b1,
    int n_nodes)
{
    extern __shared__ __align__(16) float smem[];
    float* As = smem;             // [64][ASF]
    float* Bs = smem + 64 * ASF;  // [128 n][ASF k]

    const int tid = threadIdx.x;
    const int wid = tid >> 5;
    const int lane = tid & 31;
    const int m0 = blockIdx.x * 64;
    const int half = blockIdx.y;

    // ---- async copy of pre-rounded W^T half [128 x 128] ----
    {
        const float* src = g_Wt + (size_t)half * 128 * 128;
        #pragma unroll
        for (int i = 0; i < 16; i++) {
            int idx = tid + i * 256;            // 0..4095 float4 slots
            int r = idx >> 5;
            int q = idx & 31;
            cp_async16(Bs + r * ASF + q * 4, src + (size_t)r * 128 + q * 4);
        }
        asm volatile("cp.async.commit_group;" ::: "memory");
    }

    // ---- load z tile [64 x 128], round to tf32 ----
    #pragma unroll
    for (int i = 0; i < 8; i++) {
        int idx = tid + i * 256;                // 0..2047 float4 slots
        int r = idx >> 5;
        int c4 = idx & 31;
        float4 v = make_float4(0.f, 0.f, 0.f, 0.f);
        if (m0 + r < n_nodes)
            v = *(const float4*)(z + (size_t)(m0 + r) * H + c4 * 4);
        v.x = to_tf32(v.x); v.y = to_tf32(v.y);
        v.z = to_tf32(v.z); v.w = to_tf32(v.w);
        *(float4*)(As + r * ASF + c4 * 4) = v;
    }
    asm volatile("cp.async.wait_group 0;" ::: "memory");
    __syncthreads();

    // ---- compute: 8 warps, warp tile 32(M) x 32(N) ----
    const int wm = wid & 1;                     // 2 warps along M
    const int wn = wid >> 1;                    // 4 warps along N
    const int gr = lane >> 2;
    const int cc = lane & 3;

    float acc[2][4][4];
    #pragma unroll
    for (int a = 0; a < 2; a++)
        #pragma unroll
        for (int b = 0; b < 4; b++)
            #pragma unroll
            for (int c = 0; c < 4; c++) acc[a][b][c] = 0.f;

    #pragma unroll
    for (int ks = 0; ks < 16; ks++) {
        const int k0 = ks * 8 + cc;
        uint32_t a[2][4];
        #pragma unroll
        for (int mt = 0; mt < 2; mt++) {
            int row = wm * 32 + mt * 16 + gr;
            a[mt][0] = __float_as_uint(As[row * ASF + k0]);
            a[mt][1] = __float_as_uint(As[(row + 8) * ASF + k0]);
            a[mt][2] = __float_as_uint(As[row * ASF + k0 + 4]);
            a[mt][3] = __float_as_uint(As[(row + 8) * ASF + k0 + 4]);
        }
        #pragma unroll
        for (int nt = 0; nt < 4; nt++) {
            int nrow = wn * 32 + nt * 8 + gr;
            uint32_t b0 = __float_as_uint(Bs[nrow * ASF + k0]);
            uint32_t b1r = __float_as_uint(Bs[nrow * ASF + k0 + 4]);
            #pragma unroll
            for (int mt = 0; mt < 2; mt++)
                mma_tf32(acc[mt][nt], a[mt], b0, b1r);
        }
    }

    // ---- epilogue: half2 writes, b1 fused on cols < 128 ----
    #pragma unroll
    for (int mt = 0; mt < 2; mt++) {
        #pragma unroll
        for (int nt = 0; nt < 4; nt++) {
            int nloc = wn * 32 + nt * 8 + cc * 2;
            int ncol = half * 128 + nloc;
            float bx = 0.f, by = 0.f;
            if (half == 0) {
                float2 bb = __ldg((const float2*)(b1 + nloc));
                bx = bb.x; by = bb.y;
            }
            int row0 = m0 + wm * 32 + mt * 16 + gr;
            if (row0 < n_nodes) {
                __half2 v = __floats2half2_rn(acc[mt][nt][0] + bx, acc[mt][nt][1] + by);
                *(__half2*)(g_ABh + (size_t)row0 * 256 + ncol) = v;
            }
            int row1 = row0 + 8;
            if (row1 < n_nodes) {
                __half2 v = __floats2half2_rn(acc[mt][nt][2] + bx, acc[mt][nt][3] + by);
                *(__half2*)(g_ABh + (size_t)row1 * 256 + ncol) = v;
            }
        }
    }
}

#define SMEM_GEMM ((64 + 128) * ASF * 4)   // 101376 bytes

// ---------------- Edge pass: 4 edges per warp, full-warp dot ----------------
__global__ __launch_bounds__(256) void edge_kernel(
    const void* __restrict__ eli_raw,
    const float* __restrict__ W2,
    const float* __restrict__ b2,
    float* __restrict__ out,
    int E, int n_nodes)
{
    __shared__ float w2s[128];
    const int tid = threadIdx.x;
    if (tid < 128) w2s[tid] = W2[tid];
    __syncthreads();

    const int lane = tid & 31;
    const int warp = tid >> 5;
    const int e0 = (blockIdx.x * 8 + warp) * 4;
    if (e0 >= E) return;

    // lanes 0..3 load r for edges e0..e0+3; lanes 4..7 load c
    int vidx = 0;
    if (lane < 8) {
        int e = e0 + (lane & 3);
        if (e >= E) e = E - 1;
        size_t off = (lane >= 4) ? ((size_t)E + e) : (size_t)e;
        if (g_idx_is64) vidx = (int)((const long long*)eli_raw)[off];
        else            vidx = ((const int*)eli_raw)[off];
        vidx = min(max(vidx, 0), n_nodes - 1);
    }

    uint2 av[4], bv[4];
    #pragma unroll
    for (int i = 0; i < 4; i++) {
        int r = __shfl_sync(0xffffffffu, vidx, i);
        int c = __shfl_sync(0xffffffffu, vidx, 4 + i);
        av[i] = *(const uint2*)(g_ABh + (size_t)r * 256 + lane * 4);
        bv[i] = *(const uint2*)(g_ABh + (size_t)c * 256 + 128 + lane * 4);
    }

    const float4 wv = *(const float4*)(w2s + lane * 4);
    const float bias = __ldg(b2);

    #pragma unroll
    for (int i = 0; i < 4; i++) {
        float2 a0 = __half22float2(*(__half2*)&av[i].x);
        float2 a1 = __half22float2(*(__half2*)&av[i].y);
        float2 c0 = __half22float2(*(__half2*)&bv[i].x);
        float2 c1 = __half22float2(*(__half2*)&bv[i].y);
        float s = fmaxf(a0.x + c0.x, 0.f) * wv.x
                + fmaxf(a0.y + c0.y, 0.f) * wv.y
                + fmaxf(a1.x + c1.x, 0.f) * wv.z
                + fmaxf(a1.y + c1.y, 0.f) * wv.w;
        #pragma unroll
        for (int o = 16; o; o >>= 1) s += __shfl_xor_sync(0xffffffffu, s, o);
        if (lane == 0 && e0 + i < E) out[e0 + i] = s + bias;
    }
}

extern "C" void kernel_launch(void* const* d_in, const int* in_sizes, int n_in,
                              void* d_out, int out_size)
{
    const float* z   = (const float*)d_in[0];
    const void*  eli = d_in[1];
    const float* W1  = (const float*)d_in[2];
    const float* b1  = (const float*)d_in[3];
    const float* W2  = (const float*)d_in[4];
    const float* b2  = (const float*)d_in[5];
    float*       out = (float*)d_out;

    const int n_nodes = in_sizes[0] / H;
    const int E = out_size;

    int n64 = E < 1024 ? E : 1024;
    prep_kernel<<<33, 1024>>>((const long long*)eli, n64, W1);

    cudaFuncSetAttribute(node_gemm_tf32, cudaFuncAttributeMaxDynamicSharedMemorySize,
                         SMEM_GEMM);
    dim3 g1((n_nodes + 63) / 64, 2);
    node_gemm_tf32<<<g1, 256, SMEM_GEMM>>>(z, b1, n_nodes);

    int blocks = (E + 31) / 32;
    edge_kernel<<<blocks, 256>>>(eli, W2, b2, out, E, n_nodes);
}

// round 9
// speedup vs baseline: 1.2338x; 1.0142x over previous
#include <cuda_runtime.h>
#include <cuda_fp16.h>
#include <cstdint>

#define H 128
#define NMAX 100000

// Scratch: per-node A = z@W1_top + b1 (cols 0..127), B = z@W1_bot (cols 128..255), fp16
__device__ __align__(16) __half g_ABh[(size_t)NMAX * 256];
__device__ int g_idx_is64;
// Pre-transposed, tf32-rounded Wcat^T: layout [n][k], n in [0,256), k in [0,128)
__device__ __align__(16) float g_Wt[256 * 128];

__device__ __forceinline__ float to_tf32(float x) {
    float r; asm("cvt.rna.tf32.f32 %0, %1;" : "=f"(r) : "f"(x)); return r;
}

// ---------------- merged prep: block 0 detects index dtype, blocks 1..32 build W^T ----------------
__global__ void prep_kernel(const long long* __restrict__ idxp, int n64,
                            const float* __restrict__ W1) {
    if (blockIdx.x == 0) {
        int bad = 0;
        for (int i = threadIdx.x; i < n64; i += blockDim.x) {
            long long v = idxp[i];
            if (v < 0 || v >= NMAX) bad = 1;
        }
        bad = __syncthreads_or(bad);
        if (threadIdx.x == 0) g_idx_is64 = bad ? 0 : 1;
    } else {
        int idx = (blockIdx.x - 1) * blockDim.x + threadIdx.x;   // 0..32767
        int n = idx & 255;
        int k = idx >> 8;
        float v = (n < 128) ? W1[(size_t)k * 128 + n]
                            : W1[(size_t)(k + 128) * 128 + (n - 128)];
        g_Wt[(size_t)n * 128 + k] = to_tf32(v);
    }
}

// ---------------- persistent tf32 tensor-core GEMM ----------------
// CTA: loads W half once, grid-strides over M-tiles of 64 rows. 2 CTAs/SM.
#define ASF 132   // fp32 words per SMEM row (132 mod 32 = 4 -> conflict-free frags)

__device__ __forceinline__ void mma_tf32(float* d, const uint32_t* a,
                                         uint32_t b0, uint32_t b1) {
    asm volatile(
        "mma.sync.aligned.m16n8k8.row.col.f32.tf32.tf32.f32 "
        "{%0,%1,%2,%3}, {%4,%5,%6,%7}, {%8,%9}, {%0,%1,%2,%3};"
        : "+f"(d[0]), "+f"(d[1]), "+f"(d[2]), "+f"(d[3])
        : "r"(a[0]), "r"(a[1]), "r"(a[2]), "r"(a[3]), "r"(b0), "r"(b1));
}

__device__ __forceinline__ void cp_async16(void* smem_dst, const void* gsrc) {
    uint32_t a;
    asm("{ .reg .u64 t; cvta.to.shared.u64 t, %1; cvt.u32.u64 %0, t; }"
        : "=r"(a) : "l"(smem_dst));
    asm volatile("cp.async.cg.shared.global [%0], [%1], 16;" :: "r"(a), "l"(gsrc) : "memory");
}

__global__ __launch_bounds__(256, 2) void node_gemm_tf32(
    const float* __restrict__ z,
    const float* __restrict__ b1,
    int n_nodes)
{
    extern __shared__ __align__(16) float smem[];
    float* As = smem;             // [64][ASF]
    float* Bs = smem + 64 * ASF;  // [128 n][ASF k]

    const int tid = threadIdx.x;
    const int wid = tid >> 5;
    const int lane = tid & 31;
    const int half = blockIdx.y;
    const int n_tiles = (n_nodes + 63) >> 6;

    // ---- async copy of pre-rounded W^T half [128 x 128] (ONCE per CTA) ----
    {
        const float* src = g_Wt + (size_t)half * 128 * 128;
        #pragma unroll
        for (int i = 0; i < 16; i++) {
            int idx = tid + i * 256;            // 0..4095 float4 slots
            int r = idx >> 5;
            int q = idx & 31;
            cp_async16(Bs + r * ASF + q * 4, src + (size_t)r * 128 + q * 4);
        }
        asm volatile("cp.async.commit_group;" ::: "memory");
        asm volatile("cp.async.wait_group 0;" ::: "memory");
    }

    const int wm = wid & 1;                     // 2 warps along M
    const int wn = wid >> 1;                    // 4 warps along N
    const int gr = lane >> 2;
    const int cc = lane & 3;

    // preload b1 slice for this thread's columns (invariant across tiles)
    float bx = 0.f, by = 0.f;
    if (half == 0) {
        float2 bb = __ldg((const float2*)(b1 + (wn * 32 + cc * 2)));
        // NOTE: per-nt offset handled below; preload only works per nt, so keep in loop instead.
        bx = bb.x; by = bb.y;   // (used only as nt==0 fast path; full loads below)
    }

    for (int mt = blockIdx.x; mt < n_tiles; mt += gridDim.x) {
        const int m0 = mt * 64;

        // ---- load z tile [64 x 128], round to tf32 ----
        #pragma unroll
        for (int i = 0; i < 8; i++) {
            int idx = tid + i * 256;            // 0..2047 float4 slots
            int r = idx >> 5;
            int c4 = idx & 31;
            float4 v = make_float4(0.f, 0.f, 0.f, 0.f);
            if (m0 + r < n_nodes)
                v = *(const float4*)(z + (size_t)(m0 + r) * H + c4 * 4);
            v.x = to_tf32(v.x); v.y = to_tf32(v.y);
            v.z = to_tf32(v.z); v.w = to_tf32(v.w);
            *(float4*)(As + r * ASF + c4 * 4) = v;
        }
        __syncthreads();

        float acc[2][4][4];
        #pragma unroll
        for (int a = 0; a < 2; a++)
            #pragma unroll
            for (int b = 0; b < 4; b++)
                #pragma unroll
                for (int c = 0; c < 4; c++) acc[a][b][c] = 0.f;

        #pragma unroll
        for (int ks = 0; ks < 16; ks++) {
            const int k0 = ks * 8 + cc;
            uint32_t a[2][4];
            #pragma unroll
            for (int mtile = 0; mtile < 2; mtile++) {
                int row = wm * 32 + mtile * 16 + gr;
                a[mtile][0] = __float_as_uint(As[row * ASF + k0]);
                a[mtile][1] = __float_as_uint(As[(row + 8) * ASF + k0]);
                a[mtile][2] = __float_as_uint(As[row * ASF + k0 + 4]);
                a[mtile][3] = __float_as_uint(As[(row + 8) * ASF + k0 + 4]);
            }
            #pragma unroll
            for (int nt = 0; nt < 4; nt++) {
                int nrow = wn * 32 + nt * 8 + gr;
                uint32_t b0 = __float_as_uint(Bs[nrow * ASF + k0]);
                uint32_t b1r = __float_as_uint(Bs[nrow * ASF + k0 + 4]);
                #pragma unroll
                for (int mtile = 0; mtile < 2; mtile++)
                    mma_tf32(acc[mtile][nt], a[mtile], b0, b1r);
            }
        }

        // ---- epilogue: half2 writes, b1 fused on cols < 128 ----
        #pragma unroll
        for (int mtile = 0; mtile < 2; mtile++) {
            #pragma unroll
            for (int nt = 0; nt < 4; nt++) {
                int nloc = wn * 32 + nt * 8 + cc * 2;
                int ncol = half * 128 + nloc;
                float ax = 0.f, ay = 0.f;
                if (half == 0) {
                    float2 bb = __ldg((const float2*)(b1 + nloc));
                    ax = bb.x; ay = bb.y;
                }
                int row0 = m0 + wm * 32 + mtile * 16 + gr;
                if (row0 < n_nodes) {
                    __half2 v = __floats2half2_rn(acc[mtile][nt][0] + ax,
                                                  acc[mtile][nt][1] + ay);
                    *(__half2*)(g_ABh + (size_t)row0 * 256 + ncol) = v;
                }
                int row1 = row0 + 8;
                if (row1 < n_nodes) {
                    __half2 v = __floats2half2_rn(acc[mtile][nt][2] + ax,
                                                  acc[mtile][nt][3] + ay);
                    *(__half2*)(g_ABh + (size_t)row1 * 256 + ncol) = v;
                }
            }
        }
        __syncthreads();   // protect As before next tile's overwrite
    }
    (void)bx; (void)by;
}

#define SMEM_GEMM ((64 + 128) * ASF * 4)   // 101376 bytes

// ---------------- Edge pass: 4 edges per warp, full-warp dot ----------------
__global__ __launch_bounds__(256) void edge_kernel(
    const void* __restrict__ eli_raw,
    const float* __restrict__ W2,
    const float* __restrict__ b2,
    float* __restrict__ out,
    int E, int n_nodes)
{
    __shared__ float w2s[128];
    const int tid = threadIdx.x;
    if (tid < 128) w2s[tid] = W2[tid];
    __syncthreads();

    const int lane = tid & 31;
    const int warp = tid >> 5;
    const int e0 = (blockIdx.x * 8 + warp) * 4;
    if (e0 >= E) return;

    // lanes 0..3 load r for edges e0..e0+3; lanes 4..7 load c
    int vidx = 0;
    if (lane < 8) {
        int e = e0 + (lane & 3);
        if (e >= E) e = E - 1;
        size_t off = (lane >= 4) ? ((size_t)E + e) : (size_t)e;
        if (g_idx_is64) vidx = (int)((const long long*)eli_raw)[off];
        else            vidx = ((const int*)eli_raw)[off];
        vidx = min(max(vidx, 0), n_nodes - 1);
    }

    uint2 av[4], bv[4];
    #pragma unroll
    for (int i = 0; i < 4; i++) {
        int r = __shfl_sync(0xffffffffu, vidx, i);
        int c = __shfl_sync(0xffffffffu, vidx, 4 + i);
        av[i] = *(const uint2*)(g_ABh + (size_t)r * 256 + lane * 4);
        bv[i] = *(const uint2*)(g_ABh + (size_t)c * 256 + 128 + lane * 4);
    }

    const float4 wv = *(const float4*)(w2s + lane * 4);
    const float bias = __ldg(b2);

    #pragma unroll
    for (int i = 0; i < 4; i++) {
        float2 a0 = __half22float2(*(__half2*)&av[i].x);
        float2 a1 = __half22float2(*(__half2*)&av[i].y);
        float2 c0 = __half22float2(*(__half2*)&bv[i].x);
        float2 c1 = __half22float2(*(__half2*)&bv[i].y);
        float s = fmaxf(a0.x + c0.x, 0.f) * wv.x
                + fmaxf(a0.y + c0.y, 0.f) * wv.y
                + fmaxf(a1.x + c1.x, 0.f) * wv.z
                + fmaxf(a1.y + c1.y, 0.f) * wv.w;
        #pragma unroll
        for (int o = 16; o; o >>= 1) s += __shfl_xor_sync(0xffffffffu, s, o);
        if (lane == 0 && e0 + i < E) out[e0 + i] = s + bias;
    }
}

extern "C" void kernel_launch(void* const* d_in, const int* in_sizes, int n_in,
                              void* d_out, int out_size)
{
    const float* z   = (const float*)d_in[0];
    const void*  eli = d_in[1];
    const float* W1  = (const float*)d_in[2];
    const float* b1  = (const float*)d_in[3];
    const float* W2  = (const float*)d_in[4];
    const float* b2  = (const float*)d_in[5];
    float*       out = (float*)d_out;

    const int n_nodes = in_sizes[0] / H;
    const int E = out_size;

    int n64 = E < 1024 ? E : 1024;
    prep_kernel<<<33, 1024>>>((const long long*)eli, n64, W1);

    cudaFuncSetAttribute(node_gemm_tf32, cudaFuncAttributeMaxDynamicSharedMemorySize,
                         SMEM_GEMM);
    dim3 g1(148, 2);
    node_gemm_tf32<<<g1, 256, SMEM_GEMM>>>(z, b1, n_nodes);

    int blocks = (E + 31) / 32;
    edge_kernel<<<blocks, 256>>>(eli, W2, b2, out, E, n_nodes);
}

// round 10
// speedup vs baseline: 1.5419x; 1.2498x over previous
#include <cuda_runtime.h>
#include <cuda_fp16.h>
#include <cstdint>

#define H 128
#define NMAX 100000

// Scratch: per-node A = z@W1_top + b1 (cols 0..127), B = z@W1_bot (cols 128..255), fp16
__device__ __align__(16) __half g_ABh[(size_t)NMAX * 256];
__device__ int g_idx_is64;
// Pre-transposed, tf32-rounded Wcat^T: layout [n][k], n in [0,256), k in [0,128)
__device__ __align__(16) float g_Wt[256 * 128];

__device__ __forceinline__ float to_tf32(float x) {
    float r; asm("cvt.rna.tf32.f32 %0, %1;" : "=f"(r) : "f"(x)); return r;
}

// ---------------- merged prep: block 0 detects index dtype, blocks 1..32 build W^T ----------------
__global__ void prep_kernel(const long long* __restrict__ idxp, int n64,
                            const float* __restrict__ W1) {
    if (blockIdx.x == 0) {
        int bad = 0;
        for (int i = threadIdx.x; i < n64; i += blockDim.x) {
            long long v = idxp[i];
            if (v < 0 || v >= NMAX) bad = 1;
        }
        bad = __syncthreads_or(bad);
        if (threadIdx.x == 0) g_idx_is64 = bad ? 0 : 1;
    } else {
        int idx = (blockIdx.x - 1) * blockDim.x + threadIdx.x;   // 0..32767
        int n = idx & 255;
        int k = idx >> 8;
        float v = (n < 128) ? W1[(size_t)k * 128 + n]
                            : W1[(size_t)(k + 128) * 128 + (n - 128)];
        g_Wt[(size_t)n * 128 + k] = to_tf32(v);
    }
}

// ---------------- persistent tf32 tensor-core GEMM with register prefetch ----------------
#define ASF 132   // fp32 words per SMEM row (132 mod 32 = 4 -> conflict-free frags)

__device__ __forceinline__ void mma_tf32(float* d, const uint32_t* a,
                                         uint32_t b0, uint32_t b1) {
    asm volatile(
        "mma.sync.aligned.m16n8k8.row.col.f32.tf32.tf32.f32 "
        "{%0,%1,%2,%3}, {%4,%5,%6,%7}, {%8,%9}, {%0,%1,%2,%3};"
        : "+f"(d[0]), "+f"(d[1]), "+f"(d[2]), "+f"(d[3])
        : "r"(a[0]), "r"(a[1]), "r"(a[2]), "r"(a[3]), "r"(b0), "r"(b1));
}

__device__ __forceinline__ void cp_async16(void* smem_dst, const void* gsrc) {
    uint32_t a;
    asm("{ .reg .u64 t; cvta.to.shared.u64 t, %1; cvt.u32.u64 %0, t; }"
        : "=r"(a) : "l"(smem_dst));
    asm volatile("cp.async.cg.shared.global [%0], [%1], 16;" :: "r"(a), "l"(gsrc) : "memory");
}

__global__ __launch_bounds__(256, 2) void node_gemm_tf32(
    const float* __restrict__ z,
    const float* __restrict__ b1,
    int n_nodes)
{
    extern __shared__ __align__(16) float smem[];
    float* As = smem;             // [64][ASF]
    float* Bs = smem + 64 * ASF;  // [128 n][ASF k]

    const int tid = threadIdx.x;
    const int wid = tid >> 5;
    const int lane = tid & 31;
    const int half = blockIdx.y;
    const int n_tiles = (n_nodes + 63) >> 6;

    // ---- async copy of pre-rounded W^T half [128 x 128] (ONCE per CTA) ----
    {
        const float* src = g_Wt + (size_t)half * 128 * 128;
        #pragma unroll
        for (int i = 0; i < 16; i++) {
            int idx = tid + i * 256;
            int r = idx >> 5;
            int q = idx & 31;
            cp_async16(Bs + r * ASF + q * 4, src + (size_t)r * 128 + q * 4);
        }
        asm volatile("cp.async.commit_group;" ::: "memory");
        asm volatile("cp.async.wait_group 0;" ::: "memory");
    }

    const int wm = wid & 1;
    const int wn = wid >> 1;
    const int gr = lane >> 2;
    const int cc = lane & 3;
    const int lr = tid >> 5;          // rows this thread loads: lr, lr+... (idx>>5 pattern)

    // thread's fixed load coordinates: 8 float4 slots, idx = tid + i*256
    // r = idx>>5 in [0,64), c4 = idx&31
    float4 v[8];
    int mt = blockIdx.x;
    if (mt < n_tiles) {
        int m0 = mt * 64;
        #pragma unroll
        for (int i = 0; i < 8; i++) {
            int idx = tid + i * 256;
            int r = idx >> 5, c4 = idx & 31;
            v[i] = make_float4(0.f, 0.f, 0.f, 0.f);
            if (m0 + r < n_nodes)
                v[i] = *(const float4*)(z + (size_t)(m0 + r) * H + c4 * 4);
        }
    }
    (void)lr;

    while (mt < n_tiles) {
        const int m0 = mt * 64;

        // ---- cvt + store current tile to As ----
        #pragma unroll
        for (int i = 0; i < 8; i++) {
            int idx = tid + i * 256;
            int r = idx >> 5, c4 = idx & 31;
            float4 t = v[i];
            t.x = to_tf32(t.x); t.y = to_tf32(t.y);
            t.z = to_tf32(t.z); t.w = to_tf32(t.w);
            *(float4*)(As + r * ASF + c4 * 4) = t;
        }
        __syncthreads();

        // ---- prefetch next tile into registers (drains during MMA) ----
        const int mt_next = mt + gridDim.x;
        if (mt_next < n_tiles) {
            int m0n = mt_next * 64;
            #pragma unroll
            for (int i = 0; i < 8; i++) {
                int idx = tid + i * 256;
                int r = idx >> 5, c4 = idx & 31;
                float4 t = make_float4(0.f, 0.f, 0.f, 0.f);
                if (m0n + r < n_nodes)
                    t = *(const float4*)(z + (size_t)(m0n + r) * H + c4 * 4);
                v[i] = t;
            }
        }

        // ---- MMA ----
        float acc[2][4][4];
        #pragma unroll
        for (int a = 0; a < 2; a++)
            #pragma unroll
            for (int b = 0; b < 4; b++)
                #pragma unroll
                for (int c = 0; c < 4; c++) acc[a][b][c] = 0.f;

        #pragma unroll
        for (int ks = 0; ks < 16; ks++) {
            const int k0 = ks * 8 + cc;
            uint32_t a[2][4];
            #pragma unroll
            for (int mtile = 0; mtile < 2; mtile++) {
                int row = wm * 32 + mtile * 16 + gr;
                a[mtile][0] = __float_as_uint(As[row * ASF + k0]);
                a[mtile][1] = __float_as_uint(As[(row + 8) * ASF + k0]);
                a[mtile][2] = __float_as_uint(As[row * ASF + k0 + 4]);
                a[mtile][3] = __float_as_uint(As[(row + 8) * ASF + k0 + 4]);
            }
            #pragma unroll
            for (int nt = 0; nt < 4; nt++) {
                int nrow = wn * 32 + nt * 8 + gr;
                uint32_t b0 = __float_as_uint(Bs[nrow * ASF + k0]);
                uint32_t b1r = __float_as_uint(Bs[nrow * ASF + k0 + 4]);
                #pragma unroll
                for (int mtile = 0; mtile < 2; mtile++)
                    mma_tf32(acc[mtile][nt], a[mtile], b0, b1r);
            }
        }

        // ---- epilogue: half2 writes, b1 fused on cols < 128 ----
        #pragma unroll
        for (int mtile = 0; mtile < 2; mtile++) {
            #pragma unroll
            for (int nt = 0; nt < 4; nt++) {
                int nloc = wn * 32 + nt * 8 + cc * 2;
                int ncol = half * 128 + nloc;
                float ax = 0.f, ay = 0.f;
                if (half == 0) {
                    float2 bb = __ldg((const float2*)(b1 + nloc));
                    ax = bb.x; ay = bb.y;
                }
                int row0 = m0 + wm * 32 + mtile * 16 + gr;
                if (row0 < n_nodes) {
                    __half2 o = __floats2half2_rn(acc[mtile][nt][0] + ax,
                                                  acc[mtile][nt][1] + ay);
                    *(__half2*)(g_ABh + (size_t)row0 * 256 + ncol) = o;
                }
                int row1 = row0 + 8;
                if (row1 < n_nodes) {
                    __half2 o = __floats2half2_rn(acc[mtile][nt][2] + ax,
                                                  acc[mtile][nt][3] + ay);
                    *(__half2*)(g_ABh + (size_t)row1 * 256 + ncol) = o;
                }
            }
        }
        __syncthreads();   // As free before next overwrite
        mt = mt_next;
    }
}

#define SMEM_GEMM ((64 + 128) * ASF * 4)   // 101376 bytes

// ---------------- Edge pass: 8 edges per warp, multi-value butterfly reduce ----------------
__device__ __forceinline__ float merge2(float a, float b, int sel, int delta) {
    float u = sel ? b : a;
    float w = sel ? a : b;
    return u + __shfl_xor_sync(0xffffffffu, w, delta);
}

__global__ __launch_bounds__(256) void edge_kernel(
    const void* __restrict__ eli_raw,
    const float* __restrict__ W2,
    const float* __restrict__ b2,
    float* __restrict__ out,
    int E, int n_nodes)
{
    __shared__ float w2s[128];
    const int tid = threadIdx.x;
    if (tid < 128) w2s[tid] = W2[tid];
    __syncthreads();

    const int lane = tid & 31;
    const int warp = tid >> 5;
    const int e0 = (blockIdx.x * 8 + warp) * 8;
    if (e0 >= E) return;

    // lanes 0..7 load r for edges e0..e0+7; lanes 8..15 load c
    int vidx = 0;
    if (lane < 16) {
        int e = e0 + (lane & 7);
        if (e >= E) e = E - 1;
        size_t off = (lane >= 8) ? ((size_t)E + e) : (size_t)e;
        if (g_idx_is64) vidx = (int)((const long long*)eli_raw)[off];
        else            vidx = ((const int*)eli_raw)[off];
        vidx = min(max(vidx, 0), n_nodes - 1);
    }

    uint2 av[8], bv[8];
    #pragma unroll
    for (int i = 0; i < 8; i++) {
        int r = __shfl_sync(0xffffffffu, vidx, i);
        int c = __shfl_sync(0xffffffffu, vidx, 8 + i);
        av[i] = *(const uint2*)(g_ABh + (size_t)r * 256 + lane * 4);
        bv[i] = *(const uint2*)(g_ABh + (size_t)c * 256 + 128 + lane * 4);
    }

    const float4 wv = *(const float4*)(w2s + lane * 4);
    const __half2 z2 = __float2half2_rn(0.f);

    float s[8];
    #pragma unroll
    for (int i = 0; i < 8; i++) {
        __half2 t0 = __hmax2(__hadd2(*(__half2*)&av[i].x, *(__half2*)&bv[i].x), z2);
        __half2 t1 = __hmax2(__hadd2(*(__half2*)&av[i].y, *(__half2*)&bv[i].y), z2);
        float2 f0 = __half22float2(t0);
        float2 f1 = __half22float2(t1);
        s[i] = fmaf(f0.x, wv.x, fmaf(f0.y, wv.y, fmaf(f1.x, wv.z, f1.y * wv.w)));
    }

    // merge 8 per-lane partials: after 3 role-swap stages + xor 8,16,
    // lane L holds the full sum for edge (L & 7).
    const int b0s = lane & 1, b1s = lane & 2, b2s = lane & 4;
    float t0 = merge2(s[0], s[1], b0s, 1);
    float t1 = merge2(s[2], s[3], b0s, 1);
    float t2 = merge2(s[4], s[5], b0s, 1);
    float t3 = merge2(s[6], s[7], b0s, 1);
    float u0 = merge2(t0, t1, b1s, 2);
    float u1 = merge2(t2, t3, b1s, 2);
    float p  = merge2(u0, u1, b2s, 4);
    p += __shfl_xor_sync(0xffffffffu, p, 8);
    p += __shfl_xor_sync(0xffffffffu, p, 16);

    if (lane < 8 && e0 + lane < E)
        out[e0 + lane] = p + __ldg(b2);
}

extern "C" void kernel_launch(void* const* d_in, const int* in_sizes, int n_in,
                              void* d_out, int out_size)
{
    const float* z   = (const float*)d_in[0];
    const void*  eli = d_in[1];
    const float* W1  = (const float*)d_in[2];
    const float* b1  = (const float*)d_in[3];
    const float* W2  = (const float*)d_in[4];
    const float* b2  = (const float*)d_in[5];
    float*       out = (float*)d_out;

    const int n_nodes = in_sizes[0] / H;
    const int E = out_size;

    int n64 = E < 1024 ? E : 1024;
    prep_kernel<<<33, 1024>>>((const long long*)eli, n64, W1);

    cudaFuncSetAttribute(node_gemm_tf32, cudaFuncAttributeMaxDynamicSharedMemorySize,
                         SMEM_GEMM);
    dim3 g1(148, 2);
    node_gemm_tf32<<<g1, 256, SMEM_GEMM>>>(z, b1, n_nodes);

    int blocks = (E + 63) / 64;
    edge_kernel<<<blocks, 256>>>(eli, W2, b2, out, E, n_nodes);
}

// round 11
// speedup vs baseline: 1.6041x; 1.0403x over previous
#include <cuda_runtime.h>
#include <cuda_fp16.h>
#include <cstdint>

#define H 128
#define NMAX 100000

// Scratch: per-node A = z@W1_top + b1 (cols 0..127), B = z@W1_bot (cols 128..255), fp16
__device__ __align__(16) __half g_ABh[(size_t)NMAX * 256];
__device__ int g_idx_is64;
// Pre-transposed, tf32-rounded Wcat^T: layout [n][k], n in [0,256), k in [0,128)
__device__ __align__(16) float g_Wt[256 * 128];

__device__ __forceinline__ float to_tf32(float x) {
    float r; asm("cvt.rna.tf32.f32 %0, %1;" : "=f"(r) : "f"(x)); return r;
}

// ---------------- merged prep: block 0 detects index dtype, blocks 1..32 build W^T ----------------
__global__ void prep_kernel(const long long* __restrict__ idxp, int n64,
                            const float* __restrict__ W1) {
    if (blockIdx.x == 0) {
        int bad = 0;
        for (int i = threadIdx.x; i < n64; i += blockDim.x) {
            long long v = idxp[i];
            if (v < 0 || v >= NMAX) bad = 1;
        }
        bad = __syncthreads_or(bad);
        if (threadIdx.x == 0) g_idx_is64 = bad ? 0 : 1;
    } else {
        int idx = (blockIdx.x - 1) * blockDim.x + threadIdx.x;   // 0..32767
        int n = idx & 255;
        int k = idx >> 8;
        float v = (n < 128) ? W1[(size_t)k * 128 + n]
                            : W1[(size_t)(k + 128) * 128 + (n - 128)];
        g_Wt[(size_t)n * 128 + k] = to_tf32(v);
    }
}

// ---------------- persistent tf32 GEMM: ldmatrix fragments + register prefetch ----------------
#define ASF 132   // fp32 words per SMEM row (132 mod 32 = 4 -> conflict-free ldmatrix)

__device__ __forceinline__ void mma_tf32(float* d, const uint32_t* a,
                                         uint32_t b0, uint32_t b1) {
    asm volatile(
        "mma.sync.aligned.m16n8k8.row.col.f32.tf32.tf32.f32 "
        "{%0,%1,%2,%3}, {%4,%5,%6,%7}, {%8,%9}, {%0,%1,%2,%3};"
        : "+f"(d[0]), "+f"(d[1]), "+f"(d[2]), "+f"(d[3])
        : "r"(a[0]), "r"(a[1]), "r"(a[2]), "r"(a[3]), "r"(b0), "r"(b1));
}

__device__ __forceinline__ uint32_t smem_u32(const void* p) {
    uint32_t a;
    asm("{ .reg .u64 t; cvta.to.shared.u64 t, %1; cvt.u32.u64 %0, t; }" : "=r"(a) : "l"(p));
    return a;
}

__device__ __forceinline__ void ldsm_x4(uint32_t* r, uint32_t saddr) {
    asm volatile("ldmatrix.sync.aligned.m8n8.x4.shared.b16 {%0,%1,%2,%3}, [%4];"
                 : "=r"(r[0]), "=r"(r[1]), "=r"(r[2]), "=r"(r[3]) : "r"(saddr));
}

__device__ __forceinline__ void cp_async16(void* smem_dst, const void* gsrc) {
    uint32_t a = smem_u32(smem_dst);
    asm volatile("cp.async.cg.shared.global [%0], [%1], 16;" :: "r"(a), "l"(gsrc) : "memory");
}

__global__ __launch_bounds__(256, 2) void node_gemm_tf32(
    const float* __restrict__ z,
    const float* __restrict__ b1,
    int n_nodes)
{
    extern __shared__ __align__(16) float smem[];
    float* As = smem;             // [64][ASF]
    float* Bs = smem + 64 * ASF;  // [128 n][ASF k]

    const int tid = threadIdx.x;
    const int wid = tid >> 5;
    const int lane = tid & 31;
    const int half = blockIdx.y;
    const int n_tiles = (n_nodes + 63) >> 6;

    // ---- async copy of pre-rounded W^T half [128 x 128] (ONCE per CTA) ----
    {
        const float* src = g_Wt + (size_t)half * 128 * 128;
        #pragma unroll
        for (int i = 0; i < 16; i++) {
            int idx = tid + i * 256;
            int r = idx >> 5;
            int q = idx & 31;
            cp_async16(Bs + r * ASF + q * 4, src + (size_t)r * 128 + q * 4);
        }
        asm volatile("cp.async.commit_group;" ::: "memory");
        asm volatile("cp.async.wait_group 0;" ::: "memory");
    }

    const int wm = wid & 1;
    const int wn = wid >> 1;
    const int gr = lane >> 2;
    const int cc = lane & 3;

    // ---- precompute ldmatrix lane addresses (SMEM positions are tile-invariant) ----
    // A (mtile t): quad q = lane>>3: row += 8*(q&1), word += 4*(q>>1)
    uint32_t aAddr[2], bAddr[2];
    {
        int lrow = (lane & 7) + 8 * ((lane >> 3) & 1);
        int lword = 4 * ((lane >> 4) & 1);
        #pragma unroll
        for (int t = 0; t < 2; t++)
            aAddr[t] = smem_u32(As + (wm * 32 + t * 16 + lrow) * ASF + lword);
        // B (nt-pair t): row += 8*(q>>1), word += 4*(q&1)
        int brow = (lane & 7) + 8 * ((lane >> 4) & 1);
        int bword = 4 * ((lane >> 3) & 1);
        #pragma unroll
        for (int t = 0; t < 2; t++)
            bAddr[t] = smem_u32(Bs + (wn * 32 + t * 16 + brow) * ASF + bword);
    }

    float4 v[8];
    int mt = blockIdx.x;
    if (mt < n_tiles) {
        int m0 = mt * 64;
        #pragma unroll
        for (int i = 0; i < 8; i++) {
            int idx = tid + i * 256;
            int r = idx >> 5, c4 = idx & 31;
            v[i] = make_float4(0.f, 0.f, 0.f, 0.f);
            if (m0 + r < n_nodes)
                v[i] = *(const float4*)(z + (size_t)(m0 + r) * H + c4 * 4);
        }
    }

    while (mt < n_tiles) {
        const int m0 = mt * 64;

        // ---- cvt + store current tile to As ----
        #pragma unroll
        for (int i = 0; i < 8; i++) {
            int idx = tid + i * 256;
            int r = idx >> 5, c4 = idx & 31;
            float4 t = v[i];
            t.x = to_tf32(t.x); t.y = to_tf32(t.y);
            t.z = to_tf32(t.z); t.w = to_tf32(t.w);
            *(float4*)(As + r * ASF + c4 * 4) = t;
        }
        __syncthreads();

        // ---- prefetch next tile into registers (drains during MMA) ----
        const int mt_next = mt + gridDim.x;
        if (mt_next < n_tiles) {
            int m0n = mt_next * 64;
            #pragma unroll
            for (int i = 0; i < 8; i++) {
                int idx = tid + i * 256;
                int r = idx >> 5, c4 = idx & 31;
                float4 t = make_float4(0.f, 0.f, 0.f, 0.f);
                if (m0n + r < n_nodes)
                    t = *(const float4*)(z + (size_t)(m0n + r) * H + c4 * 4);
                v[i] = t;
            }
        }

        // ---- MMA with ldmatrix fragment loads ----
        float acc[2][4][4];
        #pragma unroll
        for (int a = 0; a < 2; a++)
            #pragma unroll
            for (int b = 0; b < 4; b++)
                #pragma unroll
                for (int c = 0; c < 4; c++) acc[a][b][c] = 0.f;

        #pragma unroll
        for (int ks = 0; ks < 16; ks++) {
            const uint32_t kofs = ks * 32;          // 8 words = 32 bytes per ks
            uint32_t a[2][4], b[2][4];
            ldsm_x4(a[0], aAddr[0] + kofs);
            ldsm_x4(a[1], aAddr[1] + kofs);
            ldsm_x4(b[0], bAddr[0] + kofs);         // nt0 (r0,r1), nt1 (r2,r3)
            ldsm_x4(b[1], bAddr[1] + kofs);         // nt2, nt3
            #pragma unroll
            for (int t = 0; t < 2; t++) {
                #pragma unroll
                for (int mtile = 0; mtile < 2; mtile++) {
                    mma_tf32(acc[mtile][2 * t + 0], a[mtile], b[t][0], b[t][1]);
                    mma_tf32(acc[mtile][2 * t + 1], a[mtile], b[t][2], b[t][3]);
                }
            }
        }

        // ---- epilogue: half2 writes, b1 fused on cols < 128 ----
        #pragma unroll
        for (int mtile = 0; mtile < 2; mtile++) {
            #pragma unroll
            for (int nt = 0; nt < 4; nt++) {
                int nloc = wn * 32 + nt * 8 + cc * 2;
                int ncol = half * 128 + nloc;
                float ax = 0.f, ay = 0.f;
                if (half == 0) {
                    float2 bb = __ldg((const float2*)(b1 + nloc));
                    ax = bb.x; ay = bb.y;
                }
                int row0 = m0 + wm * 32 + mtile * 16 + gr;
                if (row0 < n_nodes) {
                    __half2 o = __floats2half2_rn(acc[mtile][nt][0] + ax,
                                                  acc[mtile][nt][1] + ay);
                    *(__half2*)(g_ABh + (size_t)row0 * 256 + ncol) = o;
                }
                int row1 = row0 + 8;
                if (row1 < n_nodes) {
                    __half2 o = __floats2half2_rn(acc[mtile][nt][2] + ax,
                                                  acc[mtile][nt][3] + ay);
                    *(__half2*)(g_ABh + (size_t)row1 * 256 + ncol) = o;
                }
            }
        }
        __syncthreads();   // As free before next overwrite
        mt = mt_next;
    }
}

#define SMEM_GEMM ((64 + 128) * ASF * 4)   // 101376 bytes

// ---------------- Edge pass: 8 edges per warp, multi-value butterfly reduce ----------------
__device__ __forceinline__ float merge2(float a, float b, int sel, int delta) {
    float u = sel ? b : a;
    float w = sel ? a : b;
    return u + __shfl_xor_sync(0xffffffffu, w, delta);
}

__global__ __launch_bounds__(256) void edge_kernel(
    const void* __restrict__ eli_raw,
    const float* __restrict__ W2,
    const float* __restrict__ b2,
    float* __restrict__ out,
    int E, int n_nodes)
{
    __shared__ float w2s[128];
    const int tid = threadIdx.x;
    if (tid < 128) w2s[tid] = W2[tid];
    __syncthreads();

    const int lane = tid & 31;
    const int warp = tid >> 5;
    const int e0 = (blockIdx.x * 8 + warp) * 8;
    if (e0 >= E) return;

    // lanes 0..7 load r for edges e0..e0+7; lanes 8..15 load c
    int vidx = 0;
    if (lane < 16) {
        int e = e0 + (lane & 7);
        if (e >= E) e = E - 1;
        size_t off = (lane >= 8) ? ((size_t)E + e) : (size_t)e;
        if (g_idx_is64) vidx = (int)((const long long*)eli_raw)[off];
        else            vidx = ((const int*)eli_raw)[off];
        vidx = min(max(vidx, 0), n_nodes - 1);
    }

    uint2 av[8], bv[8];
    #pragma unroll
    for (int i = 0; i < 8; i++) {
        int r = __shfl_sync(0xffffffffu, vidx, i);
        int c = __shfl_sync(0xffffffffu, vidx, 8 + i);
        av[i] = *(const uint2*)(g_ABh + (size_t)r * 256 + lane * 4);
        bv[i] = *(const uint2*)(g_ABh + (size_t)c * 256 + 128 + lane * 4);
    }

    const float4 wv = *(const float4*)(w2s + lane * 4);
    const __half2 z2 = __float2half2_rn(0.f);

    float s[8];
    #pragma unroll
    for (int i = 0; i < 8; i++) {
        __half2 t0 = __hmax2(__hadd2(*(__half2*)&av[i].x, *(__half2*)&bv[i].x), z2);
        __half2 t1 = __hmax2(__hadd2(*(__half2*)&av[i].y, *(__half2*)&bv[i].y), z2);
        float2 f0 = __half22float2(t0);
        float2 f1 = __half22float2(t1);
        s[i] = fmaf(f0.x, wv.x, fmaf(f0.y, wv.y, fmaf(f1.x, wv.z, f1.y * wv.w)));
    }

    const int b0s = lane & 1, b1s = lane & 2, b2s = lane & 4;
    float t0 = merge2(s[0], s[1], b0s, 1);
    float t1 = merge2(s[2], s[3], b0s, 1);
    float t2 = merge2(s[4], s[5], b0s, 1);
    float t3 = merge2(s[6], s[7], b0s, 1);
    float u0 = merge2(t0, t1, b1s, 2);
    float u1 = merge2(t2, t3, b1s, 2);
    float p  = merge2(u0, u1, b2s, 4);
    p += __shfl_xor_sync(0xffffffffu, p, 8);
    p += __shfl_xor_sync(0xffffffffu, p, 16);

    if (lane < 8 && e0 + lane < E)
        out[e0 + lane] = p + __ldg(b2);
}

extern "C" void kernel_launch(void* const* d_in, const int* in_sizes, int n_in,
                              void* d_out, int out_size)
{
    const float* z   = (const float*)d_in[0];
    const void*  eli = d_in[1];
    const float* W1  = (const float*)d_in[2];
    const float* b1  = (const float*)d_in[3];
    const float* W2  = (const float*)d_in[4];
    const float* b2  = (const float*)d_in[5];
    float*       out = (float*)d_out;

    const int n_nodes = in_sizes[0] / H;
    const int E = out_size;

    int n64 = E < 1024 ? E : 1024;
    prep_kernel<<<33, 1024>>>((const long long*)eli, n64, W1);

    cudaFuncSetAttribute(node_gemm_tf32, cudaFuncAttributeMaxDynamicSharedMemorySize,
                         SMEM_GEMM);
    dim3 g1(148, 2);
    node_gemm_tf32<<<g1, 256, SMEM_GEMM>>>(z, b1, n_nodes);

    int blocks = (E + 63) / 64;
    edge_kernel<<<blocks, 256>>>(eli, W2, b2, out, E, n_nodes);
}

// round 13
// speedup vs baseline: 1.7041x; 1.0624x over previous
#include <cuda_runtime.h>
#include <cuda_fp16.h>
#include <cstdint>

#define H 128
#define NMAX 100000

// Scratch: per-node A = z@W1_top + b1 (cols 0..127), B = z@W1_bot (cols 128..255), fp16
__device__ __align__(16) __half g_ABh[(size_t)NMAX * 256];
// Pre-transposed, tf32-rounded Wcat^T: layout [n][k], n in [0,256), k in [0,128)
__device__ __align__(16) float g_Wt[256 * 128];

__device__ __forceinline__ float to_tf32(float x) {
    float r; asm("cvt.rna.tf32.f32 %0, %1;" : "=f"(r) : "f"(x)); return r;
}

// ---------------- prep: build W^T (tf32-rounded, transposed) ----------------
__global__ void prep_kernel(const float* __restrict__ W1) {
    int idx = blockIdx.x * blockDim.x + threadIdx.x;   // 0..32767
    int n = idx & 255;
    int k = idx >> 8;
    float v = (n < 128) ? W1[(size_t)k * 128 + n]
                        : W1[(size_t)(k + 128) * 128 + (n - 128)];
    g_Wt[(size_t)n * 128 + k] = to_tf32(v);
}

// ---------------- persistent tf32 GEMM: ldmatrix + register prefetch + staged epilogue ----------------
#define ASF 132   // fp32 words per SMEM row (132 mod 32 = 4 -> conflict-free ldmatrix)

__device__ __forceinline__ void mma_tf32(float* d, const uint32_t* a,
                                         uint32_t b0, uint32_t b1) {
    asm volatile(
        "mma.sync.aligned.m16n8k8.row.col.f32.tf32.tf32.f32 "
        "{%0,%1,%2,%3}, {%4,%5,%6,%7}, {%8,%9}, {%0,%1,%2,%3};"
        : "+f"(d[0]), "+f"(d[1]), "+f"(d[2]), "+f"(d[3])
        : "r"(a[0]), "r"(a[1]), "r"(a[2]), "r"(a[3]), "r"(b0), "r"(b1));
}

__device__ __forceinline__ uint32_t smem_u32(const void* p) {
    uint32_t a;
    asm("{ .reg .u64 t; cvta.to.shared.u64 t, %1; cvt.u32.u64 %0, t; }" : "=r"(a) : "l"(p));
    return a;
}

__device__ __forceinline__ void ldsm_x4(uint32_t* r, uint32_t saddr) {
    asm volatile("ldmatrix.sync.aligned.m8n8.x4.shared.b16 {%0,%1,%2,%3}, [%4];"
                 : "=r"(r[0]), "=r"(r[1]), "=r"(r[2]), "=r"(r[3]) : "r"(saddr));
}

__device__ __forceinline__ void cp_async16(void* smem_dst, const void* gsrc) {
    uint32_t a = smem_u32(smem_dst);
    asm volatile("cp.async.cg.shared.global [%0], [%1], 16;" :: "r"(a), "l"(gsrc) : "memory");
}

__global__ __launch_bounds__(256, 2) void node_gemm_tf32(
    const float* __restrict__ z,
    const float* __restrict__ b1,
    int n_nodes)
{
    extern __shared__ __align__(16) float smem[];
    float* As = smem;             // [64][ASF] fp32 z-tile; reused as fp16 staging [64][264]
    float* Bs = smem + 64 * ASF;  // [128 n][ASF k]
    __half* stg = (__half*)As;    // staging: 64 rows x 264 halves (132 words) = same footprint

    const int tid = threadIdx.x;
    const int wid = tid >> 5;
    const int lane = tid & 31;
    const int half = blockIdx.y;
    const int n_tiles = (n_nodes + 63) >> 6;

    // ---- async copy of pre-rounded W^T half [128 x 128] (ONCE per CTA) ----
    {
        const float* src = g_Wt + (size_t)half * 128 * 128;
        #pragma unroll
        for (int i = 0; i < 16; i++) {
            int idx = tid + i * 256;
            int r = idx >> 5;
            int q = idx & 31;
            cp_async16(Bs + r * ASF + q * 4, src + (size_t)r * 128 + q * 4);
        }
        asm volatile("cp.async.commit_group;" ::: "memory");
        asm volatile("cp.async.wait_group 0;" ::: "memory");
    }

    const int wm = wid & 1;
    const int wn = wid >> 1;
    const int gr = lane >> 2;
    const int cc = lane & 3;

    // ---- precompute ldmatrix lane addresses ----
    uint32_t aAddr[2], bAddr[2];
    {
        int lrow = (lane & 7) + 8 * ((lane >> 3) & 1);
        int lword = 4 * ((lane >> 4) & 1);
        #pragma unroll
        for (int t = 0; t < 2; t++)
            aAddr[t] = smem_u32(As + (wm * 32 + t * 16 + lrow) * ASF + lword);
        int brow = (lane & 7) + 8 * ((lane >> 4) & 1);
        int bword = 4 * ((lane >> 3) & 1);
        #pragma unroll
        for (int t = 0; t < 2; t++)
            bAddr[t] = smem_u32(Bs + (wn * 32 + t * 16 + brow) * ASF + bword);
    }

    // b1 values for this thread's columns (tile-invariant)
    float bxy[4][2];
    #pragma unroll
    for (int nt = 0; nt < 4; nt++) {
        bxy[nt][0] = 0.f; bxy[nt][1] = 0.f;
        if (half == 0) {
            float2 bb = __ldg((const float2*)(b1 + (wn * 32 + nt * 8 + cc * 2)));
            bxy[nt][0] = bb.x; bxy[nt][1] = bb.y;
        }
    }

    float4 v[8];
    int mt = blockIdx.x;
    if (mt < n_tiles) {
        int m0 = mt * 64;
        #pragma unroll
        for (int i = 0; i < 8; i++) {
            int idx = tid + i * 256;
            int r = idx >> 5, c4 = idx & 31;
            v[i] = make_float4(0.f, 0.f, 0.f, 0.f);
            if (m0 + r < n_nodes)
                v[i] = *(const float4*)(z + (size_t)(m0 + r) * H + c4 * 4);
        }
    }

    while (mt < n_tiles) {
        const int m0 = mt * 64;

        // ---- cvt + store current tile to As ----
        #pragma unroll
        for (int i = 0; i < 8; i++) {
            int idx = tid + i * 256;
            int r = idx >> 5, c4 = idx & 31;
            float4 t = v[i];
            t.x = to_tf32(t.x); t.y = to_tf32(t.y);
            t.z = to_tf32(t.z); t.w = to_tf32(t.w);
            *(float4*)(As + r * ASF + c4 * 4) = t;
        }
        __syncthreads();

        // ---- prefetch next tile into registers (drains during MMA) ----
        const int mt_next = mt + gridDim.x;
        if (mt_next < n_tiles) {
            int m0n = mt_next * 64;
            #pragma unroll
            for (int i = 0; i < 8; i++) {
                int idx = tid + i * 256;
                int r = idx >> 5, c4 = idx & 31;
                float4 t = make_float4(0.f, 0.f, 0.f, 0.f);
                if (m0n + r < n_nodes)
                    t = *(const float4*)(z + (size_t)(m0n + r) * H + c4 * 4);
                v[i] = t;
            }
        }

        // ---- MMA with ldmatrix fragment loads ----
        float acc[2][4][4];
        #pragma unroll
        for (int a = 0; a < 2; a++)
            #pragma unroll
            for (int b = 0; b < 4; b++)
                #pragma unroll
                for (int c = 0; c < 4; c++) acc[a][b][c] = 0.f;

        #pragma unroll
        for (int ks = 0; ks < 16; ks++) {
            const uint32_t kofs = ks * 32;
            uint32_t a[2][4], b[2][4];
            ldsm_x4(a[0], aAddr[0] + kofs);
            ldsm_x4(a[1], aAddr[1] + kofs);
            ldsm_x4(b[0], bAddr[0] + kofs);
            ldsm_x4(b[1], bAddr[1] + kofs);
            #pragma unroll
            for (int t = 0; t < 2; t++) {
                #pragma unroll
                for (int mtile = 0; mtile < 2; mtile++) {
                    mma_tf32(acc[mtile][2 * t + 0], a[mtile], b[t][0], b[t][1]);
                    mma_tf32(acc[mtile][2 * t + 1], a[mtile], b[t][2], b[t][3]);
                }
            }
        }
        __syncthreads();   // all warps done reading As before staging overwrites it

        // ---- stage epilogue to SMEM (conflict-free), b1 fused ----
        #pragma unroll
        for (int mtile = 0; mtile < 2; mtile++) {
            #pragma unroll
            for (int nt = 0; nt < 4; nt++) {
                int nloc = wn * 32 + nt * 8 + cc * 2;
                int row0 = wm * 32 + mtile * 16 + gr;   // local row
                __half2 o0 = __floats2half2_rn(acc[mtile][nt][0] + bxy[nt][0],
                                               acc[mtile][nt][1] + bxy[nt][1]);
                *(__half2*)(stg + row0 * 264 + nloc) = o0;
                __half2 o1 = __floats2half2_rn(acc[mtile][nt][2] + bxy[nt][0],
                                               acc[mtile][nt][3] + bxy[nt][1]);
                *(__half2*)(stg + (row0 + 8) * 264 + nloc) = o1;
            }
        }
        __syncthreads();

        // ---- coalesced copy-out: 64 rows x 128 halves = 1024 uint4 ----
        #pragma unroll
        for (int i = 0; i < 4; i++) {
            int idx = tid + i * 256;                // 0..1023
            int r = idx >> 4;                       // row 0..63
            int q = idx & 15;                       // uint4 slot (8 halves each)
            int m = m0 + r;
            if (m < n_nodes)
                *(uint4*)(g_ABh + (size_t)m * 256 + (size_t)half * 128 + q * 8)
                    = *(const uint4*)(stg + r * 264 + q * 8);
        }
        __syncthreads();   // staging/As free before next tile's overwrite
        mt = mt_next;
    }
}

#define SMEM_GEMM ((64 + 128) * ASF * 4)   // 101376 bytes

// ---------------- Edge pass: 8 edges/warp, per-warp dtype detect, butterfly reduce ----------------
__device__ __forceinline__ float merge2(float a, float b, int sel, int delta) {
    float u = sel ? b : a;
    float w = sel ? a : b;
    return u + __shfl_xor_sync(0xffffffffu, w, delta);
}

__global__ __launch_bounds__(256) void edge_kernel(
    const void* __restrict__ eli_raw,
    const float* __restrict__ W2,
    const float* __restrict__ b2,
    float* __restrict__ out,
    int E, int n_nodes)
{
    __shared__ float w2s[128];
    const int tid = threadIdx.x;
    if (tid < 128) w2s[tid] = W2[tid];
    __syncthreads();

    const int lane = tid & 31;
    const int warp = tid >> 5;
    const int e0 = (blockIdx.x * 8 + warp) * 8;
    if (e0 >= E) return;

    // per-warp dtype detection: 32 int64 words in-range <=> data is int64.
    // int32 data packs 2 indices/word -> hi!=0 with prob 1-1e-5 per word;
    // false-int64 prob ~ (1e-5)^32 ~ 0.
    int is64;
    {
        int e = e0 + lane; if (e >= E) e = E - 1;
        long long w = ((const long long*)eli_raw)[e];   // word index e < E: in-bounds either way
        unsigned ok = __ballot_sync(0xffffffffu, w >= 0 && w < NMAX);
        is64 = (ok == 0xffffffffu);
    }

    // lanes 0..7 load r for edges e0..e0+7; lanes 8..15 load c
    int vidx = 0;
    if (lane < 16) {
        int e = e0 + (lane & 7);
        if (e >= E) e = E - 1;
        size_t off = (lane >= 8) ? ((size_t)E + e) : (size_t)e;
        if (is64) vidx = (int)((const long long*)eli_raw)[off];
        else      vidx = ((const int*)eli_raw)[off];
        vidx = min(max(vidx, 0), n_nodes - 1);
    }

    uint2 av[8], bv[8];
    #pragma unroll
    for (int i = 0; i < 8; i++) {
        int r = __shfl_sync(0xffffffffu, vidx, i);
        int c = __shfl_sync(0xffffffffu, vidx, 8 + i);
        av[i] = *(const uint2*)(g_ABh + (size_t)r * 256 + lane * 4);
        bv[i] = *(const uint2*)(g_ABh + (size_t)c * 256 + 128 + lane * 4);
    }

    const float4 wv = *(const float4*)(w2s + lane * 4);
    const __half2 z2 = __float2half2_rn(0.f);

    float s[8];
    #pragma unroll
    for (int i = 0; i < 8; i++) {
        __half2 t0 = __hmax2(__hadd2(*(__half2*)&av[i].x, *(__half2*)&bv[i].x), z2);
        __half2 t1 = __hmax2(__hadd2(*(__half2*)&av[i].y, *(__half2*)&bv[i].y), z2);
        float2 f0 = __half22float2(t0);
        float2 f1 = __half22float2(t1);
        s[i] = fmaf(f0.x, wv.x, fmaf(f0.y, wv.y, fmaf(f1.x, wv.z, f1.y * wv.w)));
    }

    const int b0s = lane & 1, b1s = lane & 2, b2s = lane & 4;
    float t0 = merge2(s[0], s[1], b0s, 1);
    float t1 = merge2(s[2], s[3], b0s, 1);
    float t2 = merge2(s[4], s[5], b0s, 1);
    float t3 = merge2(s[6], s[7], b0s, 1);
    float u0 = merge2(t0, t1, b1s, 2);
    float u1 = merge2(t2, t3, b1s, 2);
    float p  = merge2(u0, u1, b2s, 4);
    p += __shfl_xor_sync(0xffffffffu, p, 8);
    p += __shfl_xor_sync(0xffffffffu, p, 16);

    if (lane < 8 && e0 + lane < E)
        out[e0 + lane] = p + __ldg(b2);
}

extern "C" void kernel_launch(void* const* d_in, const int* in_sizes, int n_in,
                              void* d_out, int out_size)
{
    const float* z   = (const float*)d_in[0];
    const void*  eli = d_in[1];
    const float* W1  = (const float*)d_in[2];
    const float* b1  = (const float*)d_in[3];
    const float* W2  = (const float*)d_in[4];
    const float* b2  = (const float*)d_in[5];
    float*       out = (float*)d_out;

    const int n_nodes = in_sizes[0] / H;
    const int E = out_size;

    prep_kernel<<<32, 1024>>>(W1);

    cudaFuncSetAttribute(node_gemm_tf32, cudaFuncAttributeMaxDynamicSharedMemorySize,
                         SMEM_GEMM);
    dim3 g1(148, 2);
    node_gemm_tf32<<<g1, 256, SMEM_GEMM>>>(z, b1, n_nodes);

    int blocks = (E + 63) / 64;
    edge_kernel<<<blocks, 256>>>(eli, W2, b2, out, E, n_nodes);
}

// round 14
// speedup vs baseline: 1.7256x; 1.0126x over previous
#include <cuda_runtime.h>
#include <cuda_fp16.h>
#include <cstdint>

#define H 128
#define NMAX 100000

// Scratch: per-node A = z@W1_top + b1 (cols 0..127), B = z@W1_bot (cols 128..255), fp16
__device__ __align__(16) __half g_ABh[(size_t)NMAX * 256];
// Pre-transposed, tf32-rounded Wcat^T: layout [n][k], n in [0,256), k in [0,128)
__device__ __align__(16) float g_Wt[256 * 128];

__device__ __forceinline__ float to_tf32(float x) {
    float r; asm("cvt.rna.tf32.f32 %0, %1;" : "=f"(r) : "f"(x)); return r;
}

// ---------------- prep: build W^T (tf32-rounded, transposed) ----------------
__global__ void prep_kernel(const float* __restrict__ W1) {
    int idx = blockIdx.x * blockDim.x + threadIdx.x;   // 0..32767
    int n = idx & 255;
    int k = idx >> 8;
    float v = (n < 128) ? W1[(size_t)k * 128 + n]
                        : W1[(size_t)(k + 128) * 128 + (n - 128)];
    g_Wt[(size_t)n * 128 + k] = to_tf32(v);
}

// ---------------- persistent tf32 GEMM: ldmatrix + register prefetch + staged epilogue ----------------
#define ASF 132   // fp32 words per SMEM row (132 mod 32 = 4 -> conflict-free ldmatrix)

__device__ __forceinline__ void mma_tf32(float* d, const uint32_t* a,
                                         uint32_t b0, uint32_t b1) {
    asm volatile(
        "mma.sync.aligned.m16n8k8.row.col.f32.tf32.tf32.f32 "
        "{%0,%1,%2,%3}, {%4,%5,%6,%7}, {%8,%9}, {%0,%1,%2,%3};"
        : "+f"(d[0]), "+f"(d[1]), "+f"(d[2]), "+f"(d[3])
        : "r"(a[0]), "r"(a[1]), "r"(a[2]), "r"(a[3]), "r"(b0), "r"(b1));
}

__device__ __forceinline__ uint32_t smem_u32(const void* p) {
    uint32_t a;
    asm("{ .reg .u64 t; cvta.to.shared.u64 t, %1; cvt.u32.u64 %0, t; }" : "=r"(a) : "l"(p));
    return a;
}

__device__ __forceinline__ void ldsm_x4(uint32_t* r, uint32_t saddr) {
    asm volatile("ldmatrix.sync.aligned.m8n8.x4.shared.b16 {%0,%1,%2,%3}, [%4];"
                 : "=r"(r[0]), "=r"(r[1]), "=r"(r[2]), "=r"(r[3]) : "r"(saddr));
}

__device__ __forceinline__ void cp_async16(void* smem_dst, const void* gsrc) {
    uint32_t a = smem_u32(smem_dst);
    asm volatile("cp.async.cg.shared.global [%0], [%1], 16;" :: "r"(a), "l"(gsrc) : "memory");
}

__global__ __launch_bounds__(256, 2) void node_gemm_tf32(
    const float* __restrict__ z,
    const float* __restrict__ b1,
    int n_nodes)
{
    extern __shared__ __align__(16) float smem[];
    float* As = smem;             // [64][ASF] fp32 z-tile; reused as fp16 staging [64][264]
    float* Bs = smem + 64 * ASF;  // [128 n][ASF k]
    __half* stg = (__half*)As;    // staging: 64 rows x 264 halves (132 words) = same footprint

    const int tid = threadIdx.x;
    const int wid = tid >> 5;
    const int lane = tid & 31;
    const int half = blockIdx.y;
    const int n_tiles = (n_nodes + 63) >> 6;

    // ---- async copy of pre-rounded W^T half [128 x 128] (ONCE per CTA) ----
    {
        const float* src = g_Wt + (size_t)half * 128 * 128;
        #pragma unroll
        for (int i = 0; i < 16; i++) {
            int idx = tid + i * 256;
            int r = idx >> 5;
            int q = idx & 31;
            cp_async16(Bs + r * ASF + q * 4, src + (size_t)r * 128 + q * 4);
        }
        asm volatile("cp.async.commit_group;" ::: "memory");
        asm volatile("cp.async.wait_group 0;" ::: "memory");
    }

    const int wm = wid & 1;
    const int wn = wid >> 1;
    const int gr = lane >> 2;
    const int cc = lane & 3;

    // ---- precompute ldmatrix lane addresses ----
    uint32_t aAddr[2], bAddr[2];
    {
        int lrow = (lane & 7) + 8 * ((lane >> 3) & 1);
        int lword = 4 * ((lane >> 4) & 1);
        #pragma unroll
        for (int t = 0; t < 2; t++)
            aAddr[t] = smem_u32(As + (wm * 32 + t * 16 + lrow) * ASF + lword);
        int brow = (lane & 7) + 8 * ((lane >> 4) & 1);
        int bword = 4 * ((lane >> 3) & 1);
        #pragma unroll
        for (int t = 0; t < 2; t++)
            bAddr[t] = smem_u32(Bs + (wn * 32 + t * 16 + brow) * ASF + bword);
    }

    // b1 values for this thread's columns (tile-invariant)
    float bxy[4][2];
    #pragma unroll
    for (int nt = 0; nt < 4; nt++) {
        bxy[nt][0] = 0.f; bxy[nt][1] = 0.f;
        if (half == 0) {
            float2 bb = __ldg((const float2*)(b1 + (wn * 32 + nt * 8 + cc * 2)));
            bxy[nt][0] = bb.x; bxy[nt][1] = bb.y;
        }
    }

    float4 v[8];
    int mt = blockIdx.x;
    if (mt < n_tiles) {
        int m0 = mt * 64;
        #pragma unroll
        for (int i = 0; i < 8; i++) {
            int idx = tid + i * 256;
            int r = idx >> 5, c4 = idx & 31;
            v[i] = make_float4(0.f, 0.f, 0.f, 0.f);
            if (m0 + r < n_nodes)
                v[i] = *(const float4*)(z + (size_t)(m0 + r) * H + c4 * 4);
        }
    }

    while (mt < n_tiles) {
        const int m0 = mt * 64;

        // ---- cvt + store current tile to As ----
        #pragma unroll
        for (int i = 0; i < 8; i++) {
            int idx = tid + i * 256;
            int r = idx >> 5, c4 = idx & 31;
            float4 t = v[i];
            t.x = to_tf32(t.x); t.y = to_tf32(t.y);
            t.z = to_tf32(t.z); t.w = to_tf32(t.w);
            *(float4*)(As + r * ASF + c4 * 4) = t;
        }
        __syncthreads();

        // ---- prefetch next tile into registers (drains during MMA) ----
        const int mt_next = mt + gridDim.x;
        if (mt_next < n_tiles) {
            int m0n = mt_next * 64;
            #pragma unroll
            for (int i = 0; i < 8; i++) {
                int idx = tid + i * 256;
                int r = idx >> 5, c4 = idx & 31;
                float4 t = make_float4(0.f, 0.f, 0.f, 0.f);
                if (m0n + r < n_nodes)
                    t = *(const float4*)(z + (size_t)(m0n + r) * H + c4 * 4);
                v[i] = t;
            }
        }

        // ---- MMA with ldmatrix fragment loads ----
        float acc[2][4][4];
        #pragma unroll
        for (int a = 0; a < 2; a++)
            #pragma unroll
            for (int b = 0; b < 4; b++)
                #pragma unroll
                for (int c = 0; c < 4; c++) acc[a][b][c] = 0.f;

        #pragma unroll
        for (int ks = 0; ks < 16; ks++) {
            const uint32_t kofs = ks * 32;
            uint32_t a[2][4], b[2][4];
            ldsm_x4(a[0], aAddr[0] + kofs);
            ldsm_x4(a[1], aAddr[1] + kofs);
            ldsm_x4(b[0], bAddr[0] + kofs);
            ldsm_x4(b[1], bAddr[1] + kofs);
            #pragma unroll
            for (int t = 0; t < 2; t++) {
                #pragma unroll
                for (int mtile = 0; mtile < 2; mtile++) {
                    mma_tf32(acc[mtile][2 * t + 0], a[mtile], b[t][0], b[t][1]);
                    mma_tf32(acc[mtile][2 * t + 1], a[mtile], b[t][2], b[t][3]);
                }
            }
        }
        __syncthreads();   // all warps done reading As before staging overwrites it

        // ---- stage epilogue to SMEM (conflict-free), b1 fused ----
        #pragma unroll
        for (int mtile = 0; mtile < 2; mtile++) {
            #pragma unroll
            for (int nt = 0; nt < 4; nt++) {
                int nloc = wn * 32 + nt * 8 + cc * 2;
                int row0 = wm * 32 + mtile * 16 + gr;   // local row
                __half2 o0 = __floats2half2_rn(acc[mtile][nt][0] + bxy[nt][0],
                                               acc[mtile][nt][1] + bxy[nt][1]);
                *(__half2*)(stg + row0 * 264 + nloc) = o0;
                __half2 o1 = __floats2half2_rn(acc[mtile][nt][2] + bxy[nt][0],
                                               acc[mtile][nt][3] + bxy[nt][1]);
                *(__half2*)(stg + (row0 + 8) * 264 + nloc) = o1;
            }
        }
        __syncthreads();

        // ---- coalesced copy-out: 64 rows x 128 halves = 1024 uint4 ----
        #pragma unroll
        for (int i = 0; i < 4; i++) {
            int idx = tid + i * 256;                // 0..1023
            int r = idx >> 4;                       // row 0..63
            int q = idx & 15;                       // uint4 slot (8 halves each)
            int m = m0 + r;
            if (m < n_nodes)
                *(uint4*)(g_ABh + (size_t)m * 256 + (size_t)half * 128 + q * 8)
                    = *(const uint4*)(stg + r * 264 + q * 8);
        }
        __syncthreads();   // staging/As free before next tile's overwrite
        mt = mt_next;
    }
}

#define SMEM_GEMM ((64 + 128) * ASF * 4)   // 101376 bytes

// ---------------- Edge pass: 8 edges/warp, per-warp dtype detect, butterfly reduce ----------------
__device__ __forceinline__ float merge2(float a, float b, int sel, int delta) {
    float u = sel ? b : a;
    float w = sel ? a : b;
    return u + __shfl_xor_sync(0xffffffffu, w, delta);
}

__global__ __launch_bounds__(256) void edge_kernel(
    const void* __restrict__ eli_raw,
    const float* __restrict__ W2,
    const float* __restrict__ b2,
    float* __restrict__ out,
    int E, int n_nodes)
{
    __shared__ float w2s[128];
    const int tid = threadIdx.x;
    if (tid < 128) w2s[tid] = W2[tid];
    __syncthreads();

    const int lane = tid & 31;
    const int warp = tid >> 5;
    const int e0 = (blockIdx.x * 8 + warp) * 8;
    if (e0 >= E) return;

    // per-warp dtype detection: 32 int64 words in-range <=> data is int64.
    // int32 data packs 2 indices/word -> hi!=0 with prob 1-1e-5 per word;
    // false-int64 prob ~ (1e-5)^32 ~ 0.
    int is64;
    {
        int e = e0 + lane; if (e >= E) e = E - 1;
        long long w = ((const long long*)eli_raw)[e];   // word index e < E: in-bounds either way
        unsigned ok = __ballot_sync(0xffffffffu, w >= 0 && w < NMAX);
        is64 = (ok == 0xffffffffu);
    }

    // lanes 0..7 load r for edges e0..e0+7; lanes 8..15 load c
    int vidx = 0;
    if (lane < 16) {
        int e = e0 + (lane & 7);
        if (e >= E) e = E - 1;
        size_t off = (lane >= 8) ? ((size_t)E + e) : (size_t)e;
        if (is64) vidx = (int)((const long long*)eli_raw)[off];
        else      vidx = ((const int*)eli_raw)[off];
        vidx = min(max(vidx, 0), n_nodes - 1);
    }

    uint2 av[8], bv[8];
    #pragma unroll
    for (int i = 0; i < 8; i++) {
        int r = __shfl_sync(0xffffffffu, vidx, i);
        int c = __shfl_sync(0xffffffffu, vidx, 8 + i);
        av[i] = *(const uint2*)(g_ABh + (size_t)r * 256 + lane * 4);
        bv[i] = *(const uint2*)(g_ABh + (size_t)c * 256 + 128 + lane * 4);
    }

    const float4 wv = *(const float4*)(w2s + lane * 4);
    const __half2 z2 = __float2half2_rn(0.f);

    float s[8];
    #pragma unroll
    for (int i = 0; i < 8; i++) {
        __half2 t0 = __hmax2(__hadd2(*(__half2*)&av[i].x, *(__half2*)&bv[i].x), z2);
        __half2 t1 = __hmax2(__hadd2(*(__half2*)&av[i].y, *(__half2*)&bv[i].y), z2);
        float2 f0 = __half22float2(t0);
        float2 f1 = __half22float2(t1);
        s[i] = fmaf(f0.x, wv.x, fmaf(f0.y, wv.y, fmaf(f1.x, wv.z, f1.y * wv.w)));
    }

    const int b0s = lane & 1, b1s = lane & 2, b2s = lane & 4;
    float t0 = merge2(s[0], s[1], b0s, 1);
    float t1 = merge2(s[2], s[3], b0s, 1);
    float t2 = merge2(s[4], s[5], b0s, 1);
    float t3 = merge2(s[6], s[7], b0s, 1);
    float u0 = merge2(t0, t1, b1s, 2);
    float u1 = merge2(t2, t3, b1s, 2);
    float p  = merge2(u0, u1, b2s, 4);
    p += __shfl_xor_sync(0xffffffffu, p, 8);
    p += __shfl_xor_sync(0xffffffffu, p, 16);

    if (lane < 8 && e0 + lane < E)
        out[e0 + lane] = p + __ldg(b2);
}

extern "C" void kernel_launch(void* const* d_in, const int* in_sizes, int n_in,
                              void* d_out, int out_size)
{
    const float* z   = (const float*)d_in[0];
    const void*  eli = d_in[1];
    const float* W1  = (const float*)d_in[2];
    const float* b1  = (const float*)d_in[3];
    const float* W2  = (const float*)d_in[4];
    const float* b2  = (const float*)d_in[5];
    float*       out = (float*)d_out;

    const int n_nodes = in_sizes[0] / H;
    const int E = out_size;

    prep_kernel<<<32, 1024>>>(W1);

    cudaFuncSetAttribute(node_gemm_tf32, cudaFuncAttributeMaxDynamicSharedMemorySize,
                         SMEM_GEMM);
    dim3 g1(148, 2);
    node_gemm_tf32<<<g1, 256, SMEM_GEMM>>>(z, b1, n_nodes);

    int blocks = (E + 63) / 64;
    edge_kernel<<<blocks, 256>>>(eli, W2, b2, out, E, n_nodes);
}